// round 8
// baseline (speedup 1.0000x reference)
#include <cuda_runtime.h>
#include <cuda_bf16.h>
#include <cstdint>
#include <math.h>

// Problem constants (fixed: B=4, T=2048, H=2048)
#define BB 4
#define TT 2048
#define HH 2048
#define MM (BB*TT)              // 8192 rows
#define CHUNK 128
#define NCHUNK (TT/CHUNK)       // 16 chunks

// ---------------------------------------------------------------------------
// Scratch (device globals — no runtime allocation allowed)
// ---------------------------------------------------------------------------
__device__ float g_gate[(size_t)MM*HH];   // raw i -> sigmoid(f) after part1
__device__ float g_v[(size_t)MM*HH];      // raw f -> swiglu value after part1
__device__ float g_gp[(size_t)MM*HH];     // raw g projection
__device__ float g_o[(size_t)MM*HH];      // scan output
__device__ float g_Ac[BB*NCHUNK*HH];
__device__ float g_Bc[BB*NCHUNK*HH];
__device__ float g_cr[BB*NCHUNK*HH];
// int8 2-limb quantized operands
__device__ int8_t g_X0[(size_t)MM*HH];    // X limb0 (reused for normed o)
__device__ int8_t g_X1[(size_t)MM*HH];    // X limb1
__device__ int8_t g_W0[4][(size_t)HH*HH];
__device__ int8_t g_W1[4][(size_t)HH*HH];
__device__ float  g_sx[MM];               // per-row scale of X / normed o
__device__ float  g_sw[4][HH];            // per-row scale of each W

__device__ __forceinline__ float sigf(float x) { return 1.0f/(1.0f+__expf(-x)); }

// ---------------------------------------------------------------------------
// PTX helpers (sm_80-era -> valid on compute_100)
// ---------------------------------------------------------------------------
__device__ __forceinline__ uint32_t smem_u32(const void* p) {
    uint32_t a; asm("{ .reg .u64 t; cvta.to.shared.u64 t, %1; cvt.u32.u64 %0, t; }" : "=r"(a) : "l"(p));
    return a;
}
__device__ __forceinline__ void cp16(uint32_t saddr, const void* g) {
    asm volatile("cp.async.cg.shared.global [%0], [%1], 16;" :: "r"(saddr), "l"(g));
}
#define CP_COMMIT() asm volatile("cp.async.commit_group;" ::: "memory")
#define CP_WAIT0()  asm volatile("cp.async.wait_group 0;" ::: "memory")

__device__ __forceinline__ void ldm_x4(uint32_t a, uint32_t* r) {
    asm volatile("ldmatrix.sync.aligned.m8n8.x4.shared.b16 {%0,%1,%2,%3}, [%4];"
        : "=r"(r[0]), "=r"(r[1]), "=r"(r[2]), "=r"(r[3]) : "r"(a));
}
// s8 MMA: m16n8k32, s32 accumulate
__device__ __forceinline__ void mma_s8(int* c, const uint32_t* a, const uint32_t* b) {
    asm volatile("mma.sync.aligned.m16n8k32.row.col.s32.s8.s8.s32 "
        "{%0,%1,%2,%3}, {%4,%5,%6,%7}, {%8,%9}, {%0,%1,%2,%3};"
        : "+r"(c[0]), "+r"(c[1]), "+r"(c[2]), "+r"(c[3])
        : "r"(a[0]), "r"(a[1]), "r"(a[2]), "r"(a[3]), "r"(b[0]), "r"(b[1]));
}

__device__ __forceinline__ uint32_t pack4(int b0, int b1, int b2, int b3) {
    return (uint32_t)(b0 & 255) | ((uint32_t)(b1 & 255) << 8)
         | ((uint32_t)(b2 & 255) << 16) | ((uint32_t)(b3 & 255) << 24);
}

// ---------------------------------------------------------------------------
// Row quantizer: x ~= s*(a0 + a1/128), a0,a1 int8, s = rowmax/127.
// ---------------------------------------------------------------------------
__global__ __launch_bounds__(256) void quant_rows(
    const float* __restrict__ src, int8_t* __restrict__ d0,
    int8_t* __restrict__ d1, float* __restrict__ sarr)
{
    const int row = blockIdx.x;
    const float* x = src + (size_t)row * HH;
    const int t = threadIdx.x;
    float4 v0 = ((const float4*)x)[t*2];
    float4 v1 = ((const float4*)x)[t*2 + 1];
    float xs[8] = {v0.x, v0.y, v0.z, v0.w, v1.x, v1.y, v1.z, v1.w};
    float m = 0.f;
#pragma unroll
    for (int j = 0; j < 8; j++) m = fmaxf(m, fabsf(xs[j]));
    __shared__ float red[8];
#pragma unroll
    for (int o = 16; o; o >>= 1) m = fmaxf(m, __shfl_xor_sync(0xffffffffu, m, o));
    if ((t & 31) == 0) red[t >> 5] = m;
    __syncthreads();
    if (t < 8) {
        float mm = red[t];
#pragma unroll
        for (int o = 4; o; o >>= 1) mm = fmaxf(mm, __shfl_xor_sync(0xffu, mm, o));
        if (t == 0) red[0] = mm;
    }
    __syncthreads();
    m = red[0];
    const float s = (m > 0.f) ? m / 127.f : 1.f;
    const float inv = 127.f / fmaxf(m, 1e-30f);
    int a0[8], a1[8];
#pragma unroll
    for (int j = 0; j < 8; j++) {
        float q = xs[j] * inv;
        float r0 = rintf(q);
        a0[j] = (int)r0;
        a1[j] = (int)rintf((q - r0) * 128.f);
    }
    ((uint2*)(d0 + (size_t)row * HH))[t] = make_uint2(pack4(a0[0],a0[1],a0[2],a0[3]), pack4(a0[4],a0[5],a0[6],a0[7]));
    ((uint2*)(d1 + (size_t)row * HH))[t] = make_uint2(pack4(a1[0],a1[1],a1[2],a1[3]), pack4(a1[4],a1[5],a1[6],a1[7]));
    if (t == 0) sarr[row] = s;
}

// ===========================================================================
// 2-limb int8 GEMM on mma.sync m16n8k32: C[m,n] = sum_k A[m,k]*W[n,k]
// CTA 128x128, K-chunk 64, 8 warps (32x64), 2-stage cp.async, 2 CTAs/SM.
// C = sA[m]*sB[n]*(P + Q/128), P = a0w0, Q = a0w1 + a1w0 (a1w1 dropped).
// ===========================================================================
#define KC 64
#define ROWB 80                // conflict-free ldmatrix padding (proven R4-R6)
#define MATB (128*ROWB)        // 10240 B per matrix
#define STGB (4*MATB)          // 40960 B per stage
#define NKC (HH/KC)            // 32 k-iterations
#define NSTG 2

__global__ __launch_bounds__(256, 2) void gemm_mma(
    const int8_t* __restrict__ x0, const int8_t* __restrict__ x1,
    const float* __restrict__ sA, int wbase,
    float* __restrict__ C0, float* __restrict__ C1, float* __restrict__ C2)
{
    extern __shared__ __align__(16) char smem[];
    const uint32_t sb = smem_u32(smem);
    const int tid = threadIdx.x, lane = tid & 31, wid = tid >> 5;
    const int wm = wid >> 1, wn = wid & 1;           // 4x2 warp grid
    const int bm = blockIdx.y * 128, bn = blockIdx.x * 128;
    const int w = wbase + blockIdx.z;
    const int8_t* w0 = g_W0[w];
    const int8_t* w1 = g_W1[w];
    const float* sB = g_sw[w];
    float* C = (blockIdx.z == 0) ? C0 : (blockIdx.z == 1) ? C1 : C2;

    int P[2][8][4] = {}, Q[2][8][4] = {};

    auto load_stage = [&](int buf, int k0) {
        const uint32_t sbase = sb + buf * STGB;
#pragma unroll
        for (int i = 0; i < 8; i++) {
            int idx = i * 256 + tid;
            int mat = idx >> 9;          // 0:A0 1:A1 2:B0 3:B1
            int rem = idx & 511;
            int r = rem >> 2, vv = rem & 3;
            const int8_t* base = (mat == 0) ? x0 : (mat == 1) ? x1
                               : (mat == 2) ? w0 : w1;
            int row0 = (mat < 2) ? bm : bn;
            cp16(sbase + mat * MATB + r * ROWB + vv * 16,
                 base + (size_t)(row0 + r) * HH + k0 + vv * 16);
        }
    };

    const uint32_t aRowOff = (uint32_t)((wm * 32 + (lane & 15)) * ROWB + (lane >> 4) * 16);
    const uint32_t bRowOff = (uint32_t)((wn * 64 + ((lane >> 4) << 3) + (lane & 7)) * ROWB
                                        + ((lane >> 3) & 1) * 16);

    load_stage(0, 0);
    CP_COMMIT();
    CP_WAIT0();
    __syncthreads();

    for (int c = 0; c < NKC; c++) {
        const int buf = c & 1;
        if (c + 1 < NKC) {              // kick next stage before computing
            load_stage(buf ^ 1, (c + 1) * KC);
            CP_COMMIT();
        }
        const uint32_t s0 = sb + buf * STGB;
#pragma unroll
        for (int ks = 0; ks < 2; ks++) {
            const uint32_t kOff = ks * 32;
            uint32_t a0f[2][4], a1f[2][4];
#pragma unroll
            for (int mt = 0; mt < 2; mt++) {
                ldm_x4(s0 + 0    + mt * 16 * ROWB + kOff + aRowOff, a0f[mt]);
                ldm_x4(s0 + MATB + mt * 16 * ROWB + kOff + aRowOff, a1f[mt]);
            }
#pragma unroll
            for (int p = 0; p < 4; p++) {
                uint32_t b0f[4], b1f[4];
                ldm_x4(s0 + 2*MATB + p * 16 * ROWB + kOff + bRowOff, b0f);
                ldm_x4(s0 + 3*MATB + p * 16 * ROWB + kOff + bRowOff, b1f);
                mma_s8(P[0][2*p],   a0f[0], &b0f[0]);
                mma_s8(P[1][2*p],   a0f[1], &b0f[0]);
                mma_s8(P[0][2*p+1], a0f[0], &b0f[2]);
                mma_s8(P[1][2*p+1], a0f[1], &b0f[2]);
                mma_s8(Q[0][2*p],   a0f[0], &b1f[0]);
                mma_s8(Q[1][2*p],   a0f[1], &b1f[0]);
                mma_s8(Q[0][2*p+1], a0f[0], &b1f[2]);
                mma_s8(Q[1][2*p+1], a0f[1], &b1f[2]);
                mma_s8(Q[0][2*p],   a1f[0], &b0f[0]);
                mma_s8(Q[1][2*p],   a1f[1], &b0f[0]);
                mma_s8(Q[0][2*p+1], a1f[0], &b0f[2]);
                mma_s8(Q[1][2*p+1], a1f[1], &b0f[2]);
            }
        }
        if (c + 1 < NKC) {
            CP_WAIT0();
            __syncthreads();            // next buf ready AND this buf free
        }
    }

    // Epilogue: C = sA[r]*sB[n]*(P + Q/128)
#pragma unroll
    for (int mt = 0; mt < 2; mt++) {
        const int r0 = bm + wm * 32 + mt * 16 + (lane >> 2);
        const float sa0 = sA[r0], sa1 = sA[r0 + 8];
#pragma unroll
        for (int nt = 0; nt < 8; nt++) {
            const int col = bn + wn * 64 + nt * 8 + (lane & 3) * 2;
            const float sb0 = sB[col], sb1 = sB[col + 1];
            const int* Pp = P[mt][nt];
            const int* Qp = Q[mt][nt];
            float c0 = sa0 * sb0 * ((float)Pp[0] + (float)Qp[0] * (1.f/128.f));
            float c1 = sa0 * sb1 * ((float)Pp[1] + (float)Qp[1] * (1.f/128.f));
            float c2 = sa1 * sb0 * ((float)Pp[2] + (float)Qp[2] * (1.f/128.f));
            float c3 = sa1 * sb1 * ((float)Pp[3] + (float)Qp[3] * (1.f/128.f));
            *(float2*)&C[(size_t)r0 * HH + col]       = make_float2(c0, c1);
            *(float2*)&C[(size_t)(r0 + 8) * HH + col] = make_float2(c2, c3);
        }
    }
}

// ---------------------------------------------------------------------------
// Scan pass 1 + fused gating, float4-vectorized over d.
// ---------------------------------------------------------------------------
__global__ __launch_bounds__(256) void scan_part1()
{
    const int d4 = (blockIdx.x * blockDim.x + threadIdx.x) * 4;
    const int c = blockIdx.y, b = blockIdx.z;
    size_t base = ((size_t)(b*TT + c*CHUNK))*HH + d4;
    float4 A = make_float4(1.f,1.f,1.f,1.f);
    float4 Bv = make_float4(0.f,0.f,0.f,0.f);
#pragma unroll 2
    for (int t = 0; t < CHUNK; t++) {
        const size_t o = base + (size_t)t*HH;
        float4 iv = *(float4*)&g_gate[o];
        float4 fv = *(float4*)&g_v[o];
        float4 gt, vv;
        gt.x = sigf(fv.x); gt.y = sigf(fv.y); gt.z = sigf(fv.z); gt.w = sigf(fv.w);
        vv.x = iv.x * sigf(iv.x) * (1.f - gt.x);
        vv.y = iv.y * sigf(iv.y) * (1.f - gt.y);
        vv.z = iv.z * sigf(iv.z) * (1.f - gt.z);
        vv.w = iv.w * sigf(iv.w) * (1.f - gt.w);
        *(float4*)&g_gate[o] = gt;
        *(float4*)&g_v[o] = vv;
        Bv.x = fmaf(gt.x, Bv.x, vv.x); Bv.y = fmaf(gt.y, Bv.y, vv.y);
        Bv.z = fmaf(gt.z, Bv.z, vv.z); Bv.w = fmaf(gt.w, Bv.w, vv.w);
        A.x *= gt.x; A.y *= gt.y; A.z *= gt.z; A.w *= gt.w;
    }
    const size_t co = ((size_t)(b*NCHUNK + c))*HH + d4;
    *(float4*)&g_Ac[co] = A;
    *(float4*)&g_Bc[co] = Bv;
}
__global__ __launch_bounds__(256) void scan_part2()
{
    const int idx4 = (blockIdx.x * blockDim.x + threadIdx.x) * 4;
    const int b = idx4 / HH, d4 = idx4 % HH;
    float4 h = make_float4(0.f,0.f,0.f,0.f);
    for (int c = 0; c < NCHUNK; c++) {
        const size_t co = ((size_t)(b*NCHUNK + c))*HH + d4;
        *(float4*)&g_cr[co] = h;
        float4 A = *(float4*)&g_Ac[co];
        float4 Bv = *(float4*)&g_Bc[co];
        h.x = fmaf(A.x, h.x, Bv.x); h.y = fmaf(A.y, h.y, Bv.y);
        h.z = fmaf(A.z, h.z, Bv.z); h.w = fmaf(A.w, h.w, Bv.w);
    }
}
__global__ __launch_bounds__(256) void scan_part3()
{
    const int d4 = (blockIdx.x * blockDim.x + threadIdx.x) * 4;
    const int c = blockIdx.y, b = blockIdx.z;
    size_t base = ((size_t)(b*TT + c*CHUNK))*HH + d4;
    float4 h = *(float4*)&g_cr[((size_t)(b*NCHUNK + c))*HH + d4];
#pragma unroll 2
    for (int t = 0; t < CHUNK; t++) {
        const size_t o = base + (size_t)t*HH;
        float4 gt = *(float4*)&g_gate[o];
        float4 vv = *(float4*)&g_v[o];
        h.x = fmaf(gt.x, h.x, vv.x); h.y = fmaf(gt.y, h.y, vv.y);
        h.z = fmaf(gt.z, h.z, vv.z); h.w = fmaf(gt.w, h.w, vv.w);
        *(float4*)&g_o[o] = h;
    }
}

// ---------------------------------------------------------------------------
// Gated RMSNorm; quantizes its output row directly into g_X0/g_X1/g_sx.
// ---------------------------------------------------------------------------
__global__ __launch_bounds__(256) void norm_kernel(const float* __restrict__ w)
{
    const int m = blockIdx.x;
    const size_t row = (size_t)m * HH;
    const int t = threadIdx.x;
    float s = 0.0f;
#pragma unroll
    for (int it = 0; it < 2; it++) {
        int d4 = (it * 256 + t) * 4;
        float4 x = *(const float4*)&g_o[row + d4];
        s = fmaf(x.x, x.x, fmaf(x.y, x.y, fmaf(x.z, x.z, fmaf(x.w, x.w, s))));
    }
    __shared__ float red[8];
#pragma unroll
    for (int o = 16; o; o >>= 1) s += __shfl_xor_sync(0xffffffffu, s, o);
    if ((t & 31) == 0) red[t >> 5] = s;
    __syncthreads();
    if (t < 8) {
        float tt = red[t];
#pragma unroll
        for (int o = 4; o; o >>= 1) tt += __shfl_xor_sync(0xffu, tt, o);
        if (t == 0) red[0] = tt;
    }
    __syncthreads();
    const float rms = rsqrtf(red[0] / (float)HH + 1e-5f);

    float y[8];
    float mx = 0.f;
#pragma unroll
    for (int it = 0; it < 2; it++) {
        int d4 = (it * 256 + t) * 4;
        float4 x  = *(const float4*)&g_o[row + d4];
        float4 gp = *(const float4*)&g_gp[row + d4];
        float4 wv = *(const float4*)&w[d4];
        y[it*4+0] = x.x * rms * wv.x * gp.x * sigf(gp.x);
        y[it*4+1] = x.y * rms * wv.y * gp.y * sigf(gp.y);
        y[it*4+2] = x.z * rms * wv.z * gp.z * sigf(gp.z);
        y[it*4+3] = x.w * rms * wv.w * gp.w * sigf(gp.w);
#pragma unroll
        for (int j = 0; j < 4; j++) mx = fmaxf(mx, fabsf(y[it*4+j]));
    }
    __syncthreads();
#pragma unroll
    for (int o = 16; o; o >>= 1) mx = fmaxf(mx, __shfl_xor_sync(0xffffffffu, mx, o));
    if ((t & 31) == 0) red[t >> 5] = mx;
    __syncthreads();
    if (t < 8) {
        float mm = red[t];
#pragma unroll
        for (int o = 4; o; o >>= 1) mm = fmaxf(mm, __shfl_xor_sync(0xffu, mm, o));
        if (t == 0) red[0] = mm;
    }
    __syncthreads();
    mx = red[0];
    const float sc = (mx > 0.f) ? mx / 127.f : 1.f;
    const float inv = 127.f / fmaxf(mx, 1e-30f);
#pragma unroll
    for (int it = 0; it < 2; it++) {
        int d4 = (it * 256 + t) * 4;
        int a0[4], a1[4];
#pragma unroll
        for (int j = 0; j < 4; j++) {
            float q = y[it*4+j] * inv;
            float r0 = rintf(q);
            a0[j] = (int)r0;
            a1[j] = (int)rintf((q - r0) * 128.f);
        }
        *(uint32_t*)&g_X0[row + d4] = pack4(a0[0],a0[1],a0[2],a0[3]);
        *(uint32_t*)&g_X1[row + d4] = pack4(a1[0],a1[1],a1[2],a1[3]);
    }
    if (t == 0) g_sx[m] = sc;
}

// ---------------------------------------------------------------------------
// Launch
// ---------------------------------------------------------------------------
extern "C" void kernel_launch(void* const* d_in, const int* in_sizes, int n_in,
                              void* d_out, int out_size)
{
    const float* X  = (const float*)d_in[0];
    const float* Wi = (const float*)d_in[1];
    const float* Wf = (const float*)d_in[2];
    const float* Wg = (const float*)d_in[3];
    const float* Wo = (const float*)d_in[4];
    const float* gw = (const float*)d_in[5];
    float* out = (float*)d_out;

    cudaFuncSetAttribute(gemm_mma, cudaFuncAttributeMaxDynamicSharedMemorySize, NSTG * STGB);

    int8_t *x0, *x1, *w0b, *w1b;
    float *sx, *swb;
    cudaGetSymbolAddress((void**)&x0,  g_X0);
    cudaGetSymbolAddress((void**)&x1,  g_X1);
    cudaGetSymbolAddress((void**)&w0b, g_W0);
    cudaGetSymbolAddress((void**)&w1b, g_W1);
    cudaGetSymbolAddress((void**)&sx,  g_sx);
    cudaGetSymbolAddress((void**)&swb, g_sw);
    float *pi, *pf, *pg2;
    cudaGetSymbolAddress((void**)&pi,  g_gate);
    cudaGetSymbolAddress((void**)&pf,  g_v);
    cudaGetSymbolAddress((void**)&pg2, g_gp);

    // quantize X and the 4 weights (2-limb int8, per-row scales)
    quant_rows<<<MM, 256>>>(X, x0, x1, sx);
    quant_rows<<<HH, 256>>>(Wi, w0b + 0*(size_t)HH*HH, w1b + 0*(size_t)HH*HH, swb + 0*HH);
    quant_rows<<<HH, 256>>>(Wf, w0b + 1*(size_t)HH*HH, w1b + 1*(size_t)HH*HH, swb + 1*HH);
    quant_rows<<<HH, 256>>>(Wg, w0b + 2*(size_t)HH*HH, w1b + 2*(size_t)HH*HH, swb + 2*HH);
    quant_rows<<<HH, 256>>>(Wo, w0b + 3*(size_t)HH*HH, w1b + 3*(size_t)HH*HH, swb + 3*HH);

    // i/f/g projections (raw) via int8 tensor cores
    gemm_mma<<<dim3(HH/128, MM/128, 3), 256, NSTG*STGB>>>(x0, x1, sx, 0, pi, pf, pg2);

    // gating (fused) + linear recurrence (float4-vectorized)
    dim3 scan_grid(HH/1024, NCHUNK, BB);
    scan_part1<<<scan_grid, 256>>>();
    scan_part2<<<(BB*HH/4)/256, 256>>>();
    scan_part3<<<scan_grid, 256>>>();

    // gated RMSNorm -> quantized o (reuses g_X0/g_X1/g_sx)
    norm_kernel<<<MM, 256>>>(gw);

    // output projection -> d_out
    gemm_mma<<<dim3(HH/128, MM/128, 1), 256, NSTG*STGB>>>(x0, x1, sx, 3, out, out, out);
}

// round 9
// speedup vs baseline: 1.7403x; 1.7403x over previous
#include <cuda_runtime.h>
#include <cuda_bf16.h>
#include <cstdint>
#include <math.h>

// Problem constants (fixed: B=4, T=2048, H=2048)
#define BB 4
#define TT 2048
#define HH 2048
#define MM (BB*TT)              // 8192 rows
#define CHUNK 128
#define NCHUNK (TT/CHUNK)       // 16 chunks

// ---------------------------------------------------------------------------
// Scratch (device globals — no runtime allocation allowed)
// ---------------------------------------------------------------------------
__device__ float g_gate[(size_t)MM*HH];   // raw i -> sigmoid(f) after part1
__device__ float g_v[(size_t)MM*HH];      // raw f -> swiglu value after part1
__device__ float g_gp[(size_t)MM*HH];     // raw g projection
__device__ float g_o[(size_t)MM*HH];      // scan output
__device__ float g_Ac[BB*NCHUNK*HH];
__device__ float g_Bc[BB*NCHUNK*HH];
__device__ float g_cr[BB*NCHUNK*HH];
// int8 2-limb quantized operands
__device__ int8_t g_X0[(size_t)MM*HH];    // X limb0 (reused for normed o)
__device__ int8_t g_X1[(size_t)MM*HH];    // X limb1
__device__ int8_t g_W0[4][(size_t)HH*HH];
__device__ int8_t g_W1[4][(size_t)HH*HH];
__device__ float  g_sx[MM];               // per-row scale of X / normed o
__device__ float  g_sw[4][HH];            // per-row scale of each W

__device__ __forceinline__ float sigf(float x) { return 1.0f/(1.0f+__expf(-x)); }

// ---------------------------------------------------------------------------
// PTX helpers (sm_80-era -> valid on compute_100)
// ---------------------------------------------------------------------------
__device__ __forceinline__ uint32_t smem_u32(const void* p) {
    uint32_t a; asm("{ .reg .u64 t; cvta.to.shared.u64 t, %1; cvt.u32.u64 %0, t; }" : "=r"(a) : "l"(p));
    return a;
}
__device__ __forceinline__ void cp16(uint32_t saddr, const void* g) {
    asm volatile("cp.async.cg.shared.global [%0], [%1], 16;" :: "r"(saddr), "l"(g));
}
#define CP_COMMIT() asm volatile("cp.async.commit_group;" ::: "memory")
#define CP_WAIT1()  asm volatile("cp.async.wait_group 1;" ::: "memory")

__device__ __forceinline__ void ldm_x4(uint32_t a, uint32_t* r) {
    asm volatile("ldmatrix.sync.aligned.m8n8.x4.shared.b16 {%0,%1,%2,%3}, [%4];"
        : "=r"(r[0]), "=r"(r[1]), "=r"(r[2]), "=r"(r[3]) : "r"(a));
}
// s8 MMA: m16n8k32, s32 accumulate
__device__ __forceinline__ void mma_s8(int* c, const uint32_t* a, const uint32_t* b) {
    asm volatile("mma.sync.aligned.m16n8k32.row.col.s32.s8.s8.s32 "
        "{%0,%1,%2,%3}, {%4,%5,%6,%7}, {%8,%9}, {%0,%1,%2,%3};"
        : "+r"(c[0]), "+r"(c[1]), "+r"(c[2]), "+r"(c[3])
        : "r"(a[0]), "r"(a[1]), "r"(a[2]), "r"(a[3]), "r"(b[0]), "r"(b[1]));
}

__device__ __forceinline__ uint32_t pack4(int b0, int b1, int b2, int b3) {
    return (uint32_t)(b0 & 255) | ((uint32_t)(b1 & 255) << 8)
         | ((uint32_t)(b2 & 255) << 16) | ((uint32_t)(b3 & 255) << 24);
}

// ---------------------------------------------------------------------------
// Row quantizer: x ~= s*(a0 + a1/128), a0,a1 int8, s = rowmax/127.
// ---------------------------------------------------------------------------
__global__ __launch_bounds__(256) void quant_rows(
    const float* __restrict__ src, int8_t* __restrict__ d0,
    int8_t* __restrict__ d1, float* __restrict__ sarr)
{
    const int row = blockIdx.x;
    const float* x = src + (size_t)row * HH;
    const int t = threadIdx.x;
    float4 v0 = ((const float4*)x)[t*2];
    float4 v1 = ((const float4*)x)[t*2 + 1];
    float xs[8] = {v0.x, v0.y, v0.z, v0.w, v1.x, v1.y, v1.z, v1.w};
    float m = 0.f;
#pragma unroll
    for (int j = 0; j < 8; j++) m = fmaxf(m, fabsf(xs[j]));
    __shared__ float red[8];
#pragma unroll
    for (int o = 16; o; o >>= 1) m = fmaxf(m, __shfl_xor_sync(0xffffffffu, m, o));
    if ((t & 31) == 0) red[t >> 5] = m;
    __syncthreads();
    if (t < 8) {
        float mm = red[t];
#pragma unroll
        for (int o = 4; o; o >>= 1) mm = fmaxf(mm, __shfl_xor_sync(0xffu, mm, o));
        if (t == 0) red[0] = mm;
    }
    __syncthreads();
    m = red[0];
    const float s = (m > 0.f) ? m / 127.f : 1.f;
    const float inv = 127.f / fmaxf(m, 1e-30f);
    int a0[8], a1[8];
#pragma unroll
    for (int j = 0; j < 8; j++) {
        float q = xs[j] * inv;
        float r0 = rintf(q);
        a0[j] = (int)r0;
        a1[j] = (int)rintf((q - r0) * 128.f);
    }
    ((uint2*)(d0 + (size_t)row * HH))[t] = make_uint2(pack4(a0[0],a0[1],a0[2],a0[3]), pack4(a0[4],a0[5],a0[6],a0[7]));
    ((uint2*)(d1 + (size_t)row * HH))[t] = make_uint2(pack4(a1[0],a1[1],a1[2],a1[3]), pack4(a1[4],a1[5],a1[6],a1[7]));
    if (t == 0) sarr[row] = s;
}

// ===========================================================================
// 2-limb int8 GEMM on mma.sync m16n8k32  (EXACT R6 configuration: 1603 us)
// CTA 128x128, K-chunk 64, 8 warps (32x64), 3-stage cp.async, 1 CTA/SM.
// C = sA[m]*sB[n]*(P + Q/128), P = a0w0, Q = a0w1 + a1w0 (a1w1 dropped).
// ===========================================================================
#define KC 64
#define ROWB 80                // conflict-free ldmatrix padding (proven R4-R6)
#define MATB (128*ROWB)        // 10240 B per matrix
#define STGB (4*MATB)          // 40960 B per stage
#define NKC (HH/KC)            // 32 k-iterations
#define NSTG 3

__global__ __launch_bounds__(256, 1) void gemm_mma(
    const int8_t* __restrict__ x0, const int8_t* __restrict__ x1,
    const float* __restrict__ sA, int wbase,
    float* __restrict__ C0, float* __restrict__ C1, float* __restrict__ C2)
{
    extern __shared__ __align__(16) char smem[];
    const uint32_t sb = smem_u32(smem);
    const int tid = threadIdx.x, lane = tid & 31, wid = tid >> 5;
    const int wm = wid >> 1, wn = wid & 1;           // 4x2 warp grid
    const int bm = blockIdx.y * 128, bn = blockIdx.x * 128;
    const int w = wbase + blockIdx.z;
    const int8_t* w0 = g_W0[w];
    const int8_t* w1 = g_W1[w];
    const float* sB = g_sw[w];
    float* C = (blockIdx.z == 0) ? C0 : (blockIdx.z == 1) ? C1 : C2;

    int P[2][8][4] = {}, Q[2][8][4] = {};

    auto load_stage = [&](int buf, int k0) {
        const uint32_t sbase = sb + buf * STGB;
#pragma unroll
        for (int i = 0; i < 8; i++) {
            int idx = i * 256 + tid;
            int mat = idx >> 9;          // 0:A0 1:A1 2:B0 3:B1
            int rem = idx & 511;
            int r = rem >> 2, vv = rem & 3;
            const int8_t* base = (mat == 0) ? x0 : (mat == 1) ? x1
                               : (mat == 2) ? w0 : w1;
            int row0 = (mat < 2) ? bm : bn;
            cp16(sbase + mat * MATB + r * ROWB + vv * 16,
                 base + (size_t)(row0 + r) * HH + k0 + vv * 16);
        }
    };

    const uint32_t aRowOff = (uint32_t)((wm * 32 + (lane & 15)) * ROWB + (lane >> 4) * 16);
    const uint32_t bRowOff = (uint32_t)((wn * 64 + ((lane >> 4) << 3) + (lane & 7)) * ROWB
                                        + ((lane >> 3) & 1) * 16);

    load_stage(0, 0);      CP_COMMIT();
    load_stage(1, KC);     CP_COMMIT();

    for (int c = 0; c < NKC; c++) {
        CP_WAIT1();                         // stage c landed (c+1 may be in flight)
        __syncthreads();                    // all warps done with stage c-1's buffer
        if (c + 2 < NKC) { load_stage((c + 2) % NSTG, (c + 2) * KC); CP_COMMIT(); }
        else CP_COMMIT();                   // keep group accounting uniform

        const uint32_t s0 = sb + (c % NSTG) * STGB;
#pragma unroll
        for (int ks = 0; ks < 2; ks++) {
            const uint32_t kOff = ks * 32;
            uint32_t a0f[2][4], a1f[2][4];
#pragma unroll
            for (int mt = 0; mt < 2; mt++) {
                ldm_x4(s0 + 0    + mt * 16 * ROWB + kOff + aRowOff, a0f[mt]);
                ldm_x4(s0 + MATB + mt * 16 * ROWB + kOff + aRowOff, a1f[mt]);
            }
#pragma unroll
            for (int p = 0; p < 4; p++) {
                uint32_t b0f[4], b1f[4];
                ldm_x4(s0 + 2*MATB + p * 16 * ROWB + kOff + bRowOff, b0f);
                ldm_x4(s0 + 3*MATB + p * 16 * ROWB + kOff + bRowOff, b1f);
                mma_s8(P[0][2*p],   a0f[0], &b0f[0]);
                mma_s8(P[1][2*p],   a0f[1], &b0f[0]);
                mma_s8(P[0][2*p+1], a0f[0], &b0f[2]);
                mma_s8(P[1][2*p+1], a0f[1], &b0f[2]);
                mma_s8(Q[0][2*p],   a0f[0], &b1f[0]);
                mma_s8(Q[1][2*p],   a0f[1], &b1f[0]);
                mma_s8(Q[0][2*p+1], a0f[0], &b1f[2]);
                mma_s8(Q[1][2*p+1], a0f[1], &b1f[2]);
                mma_s8(Q[0][2*p],   a1f[0], &b0f[0]);
                mma_s8(Q[1][2*p],   a1f[1], &b0f[0]);
                mma_s8(Q[0][2*p+1], a1f[0], &b0f[2]);
                mma_s8(Q[1][2*p+1], a1f[1], &b0f[2]);
            }
        }
    }

    // Epilogue: C = sA[r]*sB[n]*(P + Q/128)
#pragma unroll
    for (int mt = 0; mt < 2; mt++) {
        const int r0 = bm + wm * 32 + mt * 16 + (lane >> 2);
        const float sa0 = sA[r0], sa1 = sA[r0 + 8];
#pragma unroll
        for (int nt = 0; nt < 8; nt++) {
            const int col = bn + wn * 64 + nt * 8 + (lane & 3) * 2;
            const float sb0 = sB[col], sb1 = sB[col + 1];
            const int* Pp = P[mt][nt];
            const int* Qp = Q[mt][nt];
            float c0 = sa0 * sb0 * ((float)Pp[0] + (float)Qp[0] * (1.f/128.f));
            float c1 = sa0 * sb1 * ((float)Pp[1] + (float)Qp[1] * (1.f/128.f));
            float c2 = sa1 * sb0 * ((float)Pp[2] + (float)Qp[2] * (1.f/128.f));
            float c3 = sa1 * sb1 * ((float)Pp[3] + (float)Qp[3] * (1.f/128.f));
            *(float2*)&C[(size_t)r0 * HH + col]       = make_float2(c0, c1);
            *(float2*)&C[(size_t)(r0 + 8) * HH + col] = make_float2(c2, c3);
        }
    }
}

// ---------------------------------------------------------------------------
// Scan pass 1 + fused gating, float4-vectorized over d.
// ---------------------------------------------------------------------------
__global__ __launch_bounds__(256) void scan_part1()
{
    const int d4 = (blockIdx.x * blockDim.x + threadIdx.x) * 4;
    const int c = blockIdx.y, b = blockIdx.z;
    size_t base = ((size_t)(b*TT + c*CHUNK))*HH + d4;
    float4 A = make_float4(1.f,1.f,1.f,1.f);
    float4 Bv = make_float4(0.f,0.f,0.f,0.f);
#pragma unroll 2
    for (int t = 0; t < CHUNK; t++) {
        const size_t o = base + (size_t)t*HH;
        float4 iv = *(float4*)&g_gate[o];
        float4 fv = *(float4*)&g_v[o];
        float4 gt, vv;
        gt.x = sigf(fv.x); gt.y = sigf(fv.y); gt.z = sigf(fv.z); gt.w = sigf(fv.w);
        vv.x = iv.x * sigf(iv.x) * (1.f - gt.x);
        vv.y = iv.y * sigf(iv.y) * (1.f - gt.y);
        vv.z = iv.z * sigf(iv.z) * (1.f - gt.z);
        vv.w = iv.w * sigf(iv.w) * (1.f - gt.w);
        *(float4*)&g_gate[o] = gt;
        *(float4*)&g_v[o] = vv;
        Bv.x = fmaf(gt.x, Bv.x, vv.x); Bv.y = fmaf(gt.y, Bv.y, vv.y);
        Bv.z = fmaf(gt.z, Bv.z, vv.z); Bv.w = fmaf(gt.w, Bv.w, vv.w);
        A.x *= gt.x; A.y *= gt.y; A.z *= gt.z; A.w *= gt.w;
    }
    const size_t co = ((size_t)(b*NCHUNK + c))*HH + d4;
    *(float4*)&g_Ac[co] = A;
    *(float4*)&g_Bc[co] = Bv;
}
__global__ __launch_bounds__(256) void scan_part2()
{
    const int idx4 = (blockIdx.x * blockDim.x + threadIdx.x) * 4;
    const int b = idx4 / HH, d4 = idx4 % HH;
    float4 h = make_float4(0.f,0.f,0.f,0.f);
    for (int c = 0; c < NCHUNK; c++) {
        const size_t co = ((size_t)(b*NCHUNK + c))*HH + d4;
        *(float4*)&g_cr[co] = h;
        float4 A = *(float4*)&g_Ac[co];
        float4 Bv = *(float4*)&g_Bc[co];
        h.x = fmaf(A.x, h.x, Bv.x); h.y = fmaf(A.y, h.y, Bv.y);
        h.z = fmaf(A.z, h.z, Bv.z); h.w = fmaf(A.w, h.w, Bv.w);
    }
}
__global__ __launch_bounds__(256) void scan_part3()
{
    const int d4 = (blockIdx.x * blockDim.x + threadIdx.x) * 4;
    const int c = blockIdx.y, b = blockIdx.z;
    size_t base = ((size_t)(b*TT + c*CHUNK))*HH + d4;
    float4 h = *(float4*)&g_cr[((size_t)(b*NCHUNK + c))*HH + d4];
#pragma unroll 2
    for (int t = 0; t < CHUNK; t++) {
        const size_t o = base + (size_t)t*HH;
        float4 gt = *(float4*)&g_gate[o];
        float4 vv = *(float4*)&g_v[o];
        h.x = fmaf(gt.x, h.x, vv.x); h.y = fmaf(gt.y, h.y, vv.y);
        h.z = fmaf(gt.z, h.z, vv.z); h.w = fmaf(gt.w, h.w, vv.w);
        *(float4*)&g_o[o] = h;
    }
}

// ---------------------------------------------------------------------------
// Gated RMSNorm; quantizes its output row directly into g_X0/g_X1/g_sx.
// ---------------------------------------------------------------------------
__global__ __launch_bounds__(256) void norm_kernel(const float* __restrict__ w)
{
    const int m = blockIdx.x;
    const size_t row = (size_t)m * HH;
    const int t = threadIdx.x;
    float s = 0.0f;
#pragma unroll
    for (int it = 0; it < 2; it++) {
        int d4 = (it * 256 + t) * 4;
        float4 x = *(const float4*)&g_o[row + d4];
        s = fmaf(x.x, x.x, fmaf(x.y, x.y, fmaf(x.z, x.z, fmaf(x.w, x.w, s))));
    }
    __shared__ float red[8];
#pragma unroll
    for (int o = 16; o; o >>= 1) s += __shfl_xor_sync(0xffffffffu, s, o);
    if ((t & 31) == 0) red[t >> 5] = s;
    __syncthreads();
    if (t < 8) {
        float tt = red[t];
#pragma unroll
        for (int o = 4; o; o >>= 1) tt += __shfl_xor_sync(0xffu, tt, o);
        if (t == 0) red[0] = tt;
    }
    __syncthreads();
    const float rms = rsqrtf(red[0] / (float)HH + 1e-5f);

    float y[8];
    float mx = 0.f;
#pragma unroll
    for (int it = 0; it < 2; it++) {
        int d4 = (it * 256 + t) * 4;
        float4 x  = *(const float4*)&g_o[row + d4];
        float4 gp = *(const float4*)&g_gp[row + d4];
        float4 wv = *(const float4*)&w[d4];
        y[it*4+0] = x.x * rms * wv.x * gp.x * sigf(gp.x);
        y[it*4+1] = x.y * rms * wv.y * gp.y * sigf(gp.y);
        y[it*4+2] = x.z * rms * wv.z * gp.z * sigf(gp.z);
        y[it*4+3] = x.w * rms * wv.w * gp.w * sigf(gp.w);
#pragma unroll
        for (int j = 0; j < 4; j++) mx = fmaxf(mx, fabsf(y[it*4+j]));
    }
    __syncthreads();
#pragma unroll
    for (int o = 16; o; o >>= 1) mx = fmaxf(mx, __shfl_xor_sync(0xffffffffu, mx, o));
    if ((t & 31) == 0) red[t >> 5] = mx;
    __syncthreads();
    if (t < 8) {
        float mm = red[t];
#pragma unroll
        for (int o = 4; o; o >>= 1) mm = fmaxf(mm, __shfl_xor_sync(0xffu, mm, o));
        if (t == 0) red[0] = mm;
    }
    __syncthreads();
    mx = red[0];
    const float sc = (mx > 0.f) ? mx / 127.f : 1.f;
    const float inv = 127.f / fmaxf(mx, 1e-30f);
#pragma unroll
    for (int it = 0; it < 2; it++) {
        int d4 = (it * 256 + t) * 4;
        int a0[4], a1[4];
#pragma unroll
        for (int j = 0; j < 4; j++) {
            float q = y[it*4+j] * inv;
            float r0 = rintf(q);
            a0[j] = (int)r0;
            a1[j] = (int)rintf((q - r0) * 128.f);
        }
        *(uint32_t*)&g_X0[row + d4] = pack4(a0[0],a0[1],a0[2],a0[3]);
        *(uint32_t*)&g_X1[row + d4] = pack4(a1[0],a1[1],a1[2],a1[3]);
    }
    if (t == 0) g_sx[m] = sc;
}

// ---------------------------------------------------------------------------
// Launch
// ---------------------------------------------------------------------------
extern "C" void kernel_launch(void* const* d_in, const int* in_sizes, int n_in,
                              void* d_out, int out_size)
{
    const float* X  = (const float*)d_in[0];
    const float* Wi = (const float*)d_in[1];
    const float* Wf = (const float*)d_in[2];
    const float* Wg = (const float*)d_in[3];
    const float* Wo = (const float*)d_in[4];
    const float* gw = (const float*)d_in[5];
    float* out = (float*)d_out;

    cudaFuncSetAttribute(gemm_mma, cudaFuncAttributeMaxDynamicSharedMemorySize, NSTG * STGB);

    int8_t *x0, *x1, *w0b, *w1b;
    float *sx, *swb;
    cudaGetSymbolAddress((void**)&x0,  g_X0);
    cudaGetSymbolAddress((void**)&x1,  g_X1);
    cudaGetSymbolAddress((void**)&w0b, g_W0);
    cudaGetSymbolAddress((void**)&w1b, g_W1);
    cudaGetSymbolAddress((void**)&sx,  g_sx);
    cudaGetSymbolAddress((void**)&swb, g_sw);
    float *pi, *pf, *pg2;
    cudaGetSymbolAddress((void**)&pi,  g_gate);
    cudaGetSymbolAddress((void**)&pf,  g_v);
    cudaGetSymbolAddress((void**)&pg2, g_gp);

    // quantize X and the 4 weights (2-limb int8, per-row scales)
    quant_rows<<<MM, 256>>>(X, x0, x1, sx);
    quant_rows<<<HH, 256>>>(Wi, w0b + 0*(size_t)HH*HH, w1b + 0*(size_t)HH*HH, swb + 0*HH);
    quant_rows<<<HH, 256>>>(Wf, w0b + 1*(size_t)HH*HH, w1b + 1*(size_t)HH*HH, swb + 1*HH);
    quant_rows<<<HH, 256>>>(Wg, w0b + 2*(size_t)HH*HH, w1b + 2*(size_t)HH*HH, swb + 2*HH);
    quant_rows<<<HH, 256>>>(Wo, w0b + 3*(size_t)HH*HH, w1b + 3*(size_t)HH*HH, swb + 3*HH);

    // i/f/g projections (raw) via int8 tensor cores
    gemm_mma<<<dim3(HH/128, MM/128, 3), 256, NSTG*STGB>>>(x0, x1, sx, 0, pi, pf, pg2);

    // gating (fused) + linear recurrence (float4-vectorized)
    dim3 scan_grid(HH/1024, NCHUNK, BB);
    scan_part1<<<scan_grid, 256>>>();
    scan_part2<<<(BB*HH/4)/256, 256>>>();
    scan_part3<<<scan_grid, 256>>>();

    // gated RMSNorm -> quantized o (reuses g_X0/g_X1/g_sx)
    norm_kernel<<<MM, 256>>>(gw);

    // output projection -> d_out
    gemm_mma<<<dim3(HH/128, MM/128, 1), 256, NSTG*STGB>>>(x0, x1, sx, 3, out, out, out);
}

// round 10
// speedup vs baseline: 1.8065x; 1.0381x over previous
#include <cuda_runtime.h>
#include <cuda_bf16.h>
#include <cstdint>
#include <math.h>

// Problem constants (fixed: B=4, T=2048, H=2048)
#define BB 4
#define TT 2048
#define HH 2048
#define MM (BB*TT)              // 8192 rows
#define CHUNK 128
#define NCHUNK (TT/CHUNK)       // 16 chunks

// ---------------------------------------------------------------------------
// Scratch (device globals — no runtime allocation allowed)
// ---------------------------------------------------------------------------
__device__ float g_gate[(size_t)MM*HH];   // raw i -> sigmoid(f) after part1
__device__ float g_v[(size_t)MM*HH];      // raw f -> swiglu value after part1
__device__ float g_gp[(size_t)MM*HH];     // raw g projection
__device__ float g_o[(size_t)MM*HH];      // scan output
__device__ float g_Ac[BB*NCHUNK*HH];
__device__ float g_Bc[BB*NCHUNK*HH];
__device__ float g_cr[BB*NCHUNK*HH];
// int8 2-limb quantized operands
__device__ int8_t g_X0[(size_t)MM*HH];    // X limb0 (reused for normed o)
__device__ int8_t g_X1[(size_t)MM*HH];    // X limb1
__device__ int8_t g_W0[4][(size_t)HH*HH];
__device__ int8_t g_W1[4][(size_t)HH*HH];
__device__ float  g_sx[MM];               // per-row scale of X / normed o
__device__ float  g_sw[4][HH];            // per-row scale of each W

// Fast approx reciprocal (single MUFU.RCP, ~2^-22 rel err)
__device__ __forceinline__ float rcpa(float x) {
    float y; asm("rcp.approx.f32 %0, %1;" : "=f"(y) : "f"(x)); return y;
}
// Fast sigmoid: 1 EX2 + 1 RCP (no div.rn sequence)
__device__ __forceinline__ float sigf(float x) {
    return rcpa(1.0f + __expf(fminf(-x, 30.0f)));
}

// ---------------------------------------------------------------------------
// PTX helpers (sm_80-era -> valid on compute_100)
// ---------------------------------------------------------------------------
__device__ __forceinline__ uint32_t smem_u32(const void* p) {
    uint32_t a; asm("{ .reg .u64 t; cvta.to.shared.u64 t, %1; cvt.u32.u64 %0, t; }" : "=r"(a) : "l"(p));
    return a;
}
__device__ __forceinline__ void cp16(uint32_t saddr, const void* g) {
    asm volatile("cp.async.cg.shared.global [%0], [%1], 16;" :: "r"(saddr), "l"(g));
}
#define CP_COMMIT() asm volatile("cp.async.commit_group;" ::: "memory")
#define CP_WAIT1()  asm volatile("cp.async.wait_group 1;" ::: "memory")

__device__ __forceinline__ void ldm_x4(uint32_t a, uint32_t* r) {
    asm volatile("ldmatrix.sync.aligned.m8n8.x4.shared.b16 {%0,%1,%2,%3}, [%4];"
        : "=r"(r[0]), "=r"(r[1]), "=r"(r[2]), "=r"(r[3]) : "r"(a));
}
// s8 MMA: m16n8k32, s32 accumulate
__device__ __forceinline__ void mma_s8(int* c, const uint32_t* a, const uint32_t* b) {
    asm volatile("mma.sync.aligned.m16n8k32.row.col.s32.s8.s8.s32 "
        "{%0,%1,%2,%3}, {%4,%5,%6,%7}, {%8,%9}, {%0,%1,%2,%3};"
        : "+r"(c[0]), "+r"(c[1]), "+r"(c[2]), "+r"(c[3])
        : "r"(a[0]), "r"(a[1]), "r"(a[2]), "r"(a[3]), "r"(b[0]), "r"(b[1]));
}

__device__ __forceinline__ uint32_t pack4(int b0, int b1, int b2, int b3) {
    return (uint32_t)(b0 & 255) | ((uint32_t)(b1 & 255) << 8)
         | ((uint32_t)(b2 & 255) << 16) | ((uint32_t)(b3 & 255) << 24);
}

// ---------------------------------------------------------------------------
// Row quantizer: x ~= s*(a0 + a1/128), a0,a1 int8, s = rowmax/127.
// ---------------------------------------------------------------------------
__global__ __launch_bounds__(256) void quant_rows(
    const float* __restrict__ src, int8_t* __restrict__ d0,
    int8_t* __restrict__ d1, float* __restrict__ sarr)
{
    const int row = blockIdx.x;
    const float* x = src + (size_t)row * HH;
    const int t = threadIdx.x;
    float4 v0 = ((const float4*)x)[t*2];
    float4 v1 = ((const float4*)x)[t*2 + 1];
    float xs[8] = {v0.x, v0.y, v0.z, v0.w, v1.x, v1.y, v1.z, v1.w};
    float m = 0.f;
#pragma unroll
    for (int j = 0; j < 8; j++) m = fmaxf(m, fabsf(xs[j]));
    __shared__ float red[8];
#pragma unroll
    for (int o = 16; o; o >>= 1) m = fmaxf(m, __shfl_xor_sync(0xffffffffu, m, o));
    if ((t & 31) == 0) red[t >> 5] = m;
    __syncthreads();
    if (t < 8) {
        float mm = red[t];
#pragma unroll
        for (int o = 4; o; o >>= 1) mm = fmaxf(mm, __shfl_xor_sync(0xffu, mm, o));
        if (t == 0) red[0] = mm;
    }
    __syncthreads();
    m = red[0];
    const float s = (m > 0.f) ? m / 127.f : 1.f;
    const float inv = 127.f * rcpa(fmaxf(m, 1e-30f));
    int a0[8], a1[8];
#pragma unroll
    for (int j = 0; j < 8; j++) {
        float q = xs[j] * inv;
        float r0 = rintf(q);
        a0[j] = (int)r0;
        a1[j] = (int)rintf((q - r0) * 128.f);
    }
    ((uint2*)(d0 + (size_t)row * HH))[t] = make_uint2(pack4(a0[0],a0[1],a0[2],a0[3]), pack4(a0[4],a0[5],a0[6],a0[7]));
    ((uint2*)(d1 + (size_t)row * HH))[t] = make_uint2(pack4(a1[0],a1[1],a1[2],a1[3]), pack4(a1[4],a1[5],a1[6],a1[7]));
    if (t == 0) sarr[row] = s;
}

// ===========================================================================
// 2-limb int8 GEMM on mma.sync m16n8k32  (EXACT R6 configuration: 1603 us)
// CTA 128x128, K-chunk 64, 8 warps (32x64), 3-stage cp.async, 1 CTA/SM.
// C = sA[m]*sB[n]*(P + Q/128), P = a0w0, Q = a0w1 + a1w0 (a1w1 dropped).
// ===========================================================================
#define KC 64
#define ROWB 80                // conflict-free ldmatrix padding (proven R4-R6)
#define MATB (128*ROWB)        // 10240 B per matrix
#define STGB (4*MATB)          // 40960 B per stage
#define NKC (HH/KC)            // 32 k-iterations
#define NSTG 3

__global__ __launch_bounds__(256, 1) void gemm_mma(
    const int8_t* __restrict__ x0, const int8_t* __restrict__ x1,
    const float* __restrict__ sA, int wbase,
    float* __restrict__ C0, float* __restrict__ C1, float* __restrict__ C2)
{
    extern __shared__ __align__(16) char smem[];
    const uint32_t sb = smem_u32(smem);
    const int tid = threadIdx.x, lane = tid & 31, wid = tid >> 5;
    const int wm = wid >> 1, wn = wid & 1;           // 4x2 warp grid
    const int bm = blockIdx.y * 128, bn = blockIdx.x * 128;
    const int w = wbase + blockIdx.z;
    const int8_t* w0 = g_W0[w];
    const int8_t* w1 = g_W1[w];
    const float* sB = g_sw[w];
    float* C = (blockIdx.z == 0) ? C0 : (blockIdx.z == 1) ? C1 : C2;

    int P[2][8][4] = {}, Q[2][8][4] = {};

    auto load_stage = [&](int buf, int k0) {
        const uint32_t sbase = sb + buf * STGB;
#pragma unroll
        for (int i = 0; i < 8; i++) {
            int idx = i * 256 + tid;
            int mat = idx >> 9;          // 0:A0 1:A1 2:B0 3:B1
            int rem = idx & 511;
            int r = rem >> 2, vv = rem & 3;
            const int8_t* base = (mat == 0) ? x0 : (mat == 1) ? x1
                               : (mat == 2) ? w0 : w1;
            int row0 = (mat < 2) ? bm : bn;
            cp16(sbase + mat * MATB + r * ROWB + vv * 16,
                 base + (size_t)(row0 + r) * HH + k0 + vv * 16);
        }
    };

    const uint32_t aRowOff = (uint32_t)((wm * 32 + (lane & 15)) * ROWB + (lane >> 4) * 16);
    const uint32_t bRowOff = (uint32_t)((wn * 64 + ((lane >> 4) << 3) + (lane & 7)) * ROWB
                                        + ((lane >> 3) & 1) * 16);

    load_stage(0, 0);      CP_COMMIT();
    load_stage(1, KC);     CP_COMMIT();

    for (int c = 0; c < NKC; c++) {
        CP_WAIT1();                         // stage c landed (c+1 may be in flight)
        __syncthreads();                    // all warps done with stage c-1's buffer
        if (c + 2 < NKC) { load_stage((c + 2) % NSTG, (c + 2) * KC); CP_COMMIT(); }
        else CP_COMMIT();                   // keep group accounting uniform

        const uint32_t s0 = sb + (c % NSTG) * STGB;
#pragma unroll
        for (int ks = 0; ks < 2; ks++) {
            const uint32_t kOff = ks * 32;
            uint32_t a0f[2][4], a1f[2][4];
#pragma unroll
            for (int mt = 0; mt < 2; mt++) {
                ldm_x4(s0 + 0    + mt * 16 * ROWB + kOff + aRowOff, a0f[mt]);
                ldm_x4(s0 + MATB + mt * 16 * ROWB + kOff + aRowOff, a1f[mt]);
            }
#pragma unroll
            for (int p = 0; p < 4; p++) {
                uint32_t b0f[4], b1f[4];
                ldm_x4(s0 + 2*MATB + p * 16 * ROWB + kOff + bRowOff, b0f);
                ldm_x4(s0 + 3*MATB + p * 16 * ROWB + kOff + bRowOff, b1f);
                mma_s8(P[0][2*p],   a0f[0], &b0f[0]);
                mma_s8(P[1][2*p],   a0f[1], &b0f[0]);
                mma_s8(P[0][2*p+1], a0f[0], &b0f[2]);
                mma_s8(P[1][2*p+1], a0f[1], &b0f[2]);
                mma_s8(Q[0][2*p],   a0f[0], &b1f[0]);
                mma_s8(Q[1][2*p],   a0f[1], &b1f[0]);
                mma_s8(Q[0][2*p+1], a0f[0], &b1f[2]);
                mma_s8(Q[1][2*p+1], a0f[1], &b1f[2]);
                mma_s8(Q[0][2*p],   a1f[0], &b0f[0]);
                mma_s8(Q[1][2*p],   a1f[1], &b0f[0]);
                mma_s8(Q[0][2*p+1], a1f[0], &b0f[2]);
                mma_s8(Q[1][2*p+1], a1f[1], &b0f[2]);
            }
        }
    }

    // Epilogue: C = sA[r]*sB[n]*(P + Q/128)
#pragma unroll
    for (int mt = 0; mt < 2; mt++) {
        const int r0 = bm + wm * 32 + mt * 16 + (lane >> 2);
        const float sa0 = sA[r0], sa1 = sA[r0 + 8];
#pragma unroll
        for (int nt = 0; nt < 8; nt++) {
            const int col = bn + wn * 64 + nt * 8 + (lane & 3) * 2;
            const float sb0 = sB[col], sb1 = sB[col + 1];
            const int* Pp = P[mt][nt];
            const int* Qp = Q[mt][nt];
            float c0 = sa0 * sb0 * ((float)Pp[0] + (float)Qp[0] * (1.f/128.f));
            float c1 = sa0 * sb1 * ((float)Pp[1] + (float)Qp[1] * (1.f/128.f));
            float c2 = sa1 * sb0 * ((float)Pp[2] + (float)Qp[2] * (1.f/128.f));
            float c3 = sa1 * sb1 * ((float)Pp[3] + (float)Qp[3] * (1.f/128.f));
            *(float2*)&C[(size_t)r0 * HH + col]       = make_float2(c0, c1);
            *(float2*)&C[(size_t)(r0 + 8) * HH + col] = make_float2(c2, c3);
        }
    }
}

// ---------------------------------------------------------------------------
// Scan pass 1 + fused gating (scalar, R6 grid) with shared-reciprocal trick:
// u=e^-f, v=e^-i, r=rcp((1+u)(1+v)); gate=(1+v)r; silu=i(1+u)r.
// 2 EX2 + 1 RCP per element (was 2 EX2 + 2 div.rn sequences).
// ---------------------------------------------------------------------------
__global__ __launch_bounds__(256) void scan_part1()
{
    const int d = blockIdx.x * blockDim.x + threadIdx.x;
    const int c = blockIdx.y, b = blockIdx.z;
    size_t base = ((size_t)(b*TT + c*CHUNK))*HH + d;
    float A = 1.0f, Bv = 0.0f;
#pragma unroll 8
    for (int t = 0; t < CHUNK; t++) {
        const size_t o = base + (size_t)t*HH;
        float iv = g_gate[o];
        float fv = g_v[o];
        float u  = __expf(fminf(-fv, 30.0f));   // e^-f
        float ve = __expf(fminf(-iv, 30.0f));   // e^-i
        float pu = 1.0f + u, pv = 1.0f + ve;
        float r  = rcpa(pu * pv);
        float gate = pv * r;                    // sigmoid(f)
        float silu = iv * pu * r;               // i*sigmoid(i)
        float vv = silu * (1.0f - gate);
        g_gate[o] = gate;
        g_v[o] = vv;
        Bv = fmaf(gate, Bv, vv);
        A *= gate;
    }
    const size_t co = ((size_t)(b*NCHUNK + c))*HH + d;
    g_Ac[co] = A; g_Bc[co] = Bv;
}
__global__ __launch_bounds__(256) void scan_part2()
{
    const int idx = blockIdx.x * blockDim.x + threadIdx.x;
    const int b = idx / HH, d = idx % HH;
    float h = 0.0f;
    for (int c = 0; c < NCHUNK; c++) {
        const size_t co = ((size_t)(b*NCHUNK + c))*HH + d;
        g_cr[co] = h;
        h = fmaf(g_Ac[co], h, g_Bc[co]);
    }
}
__global__ __launch_bounds__(256) void scan_part3()
{
    const int d = blockIdx.x * blockDim.x + threadIdx.x;
    const int c = blockIdx.y, b = blockIdx.z;
    size_t base = ((size_t)(b*TT + c*CHUNK))*HH + d;
    float h = g_cr[((size_t)(b*NCHUNK + c))*HH + d];
#pragma unroll 8
    for (int t = 0; t < CHUNK; t++) {
        const size_t o = base + (size_t)t*HH;
        h = fmaf(g_gate[o], h, g_v[o]);
        g_o[o] = h;
    }
}

// ---------------------------------------------------------------------------
// Gated RMSNorm; quantizes its output row directly into g_X0/g_X1/g_sx.
// ---------------------------------------------------------------------------
__global__ __launch_bounds__(256) void norm_kernel(const float* __restrict__ w)
{
    const int m = blockIdx.x;
    const size_t row = (size_t)m * HH;
    const int t = threadIdx.x;
    float s = 0.0f;
#pragma unroll
    for (int it = 0; it < 2; it++) {
        int d4 = (it * 256 + t) * 4;
        float4 x = *(const float4*)&g_o[row + d4];
        s = fmaf(x.x, x.x, fmaf(x.y, x.y, fmaf(x.z, x.z, fmaf(x.w, x.w, s))));
    }
    __shared__ float red[8];
#pragma unroll
    for (int o = 16; o; o >>= 1) s += __shfl_xor_sync(0xffffffffu, s, o);
    if ((t & 31) == 0) red[t >> 5] = s;
    __syncthreads();
    if (t < 8) {
        float tt = red[t];
#pragma unroll
        for (int o = 4; o; o >>= 1) tt += __shfl_xor_sync(0xffu, tt, o);
        if (t == 0) red[0] = tt;
    }
    __syncthreads();
    const float rms = rsqrtf(red[0] / (float)HH + 1e-5f);

    float y[8];
    float mx = 0.f;
#pragma unroll
    for (int it = 0; it < 2; it++) {
        int d4 = (it * 256 + t) * 4;
        float4 x  = *(const float4*)&g_o[row + d4];
        float4 gp = *(const float4*)&g_gp[row + d4];
        float4 wv = *(const float4*)&w[d4];
        y[it*4+0] = x.x * rms * wv.x * gp.x * sigf(gp.x);
        y[it*4+1] = x.y * rms * wv.y * gp.y * sigf(gp.y);
        y[it*4+2] = x.z * rms * wv.z * gp.z * sigf(gp.z);
        y[it*4+3] = x.w * rms * wv.w * gp.w * sigf(gp.w);
#pragma unroll
        for (int j = 0; j < 4; j++) mx = fmaxf(mx, fabsf(y[it*4+j]));
    }
    __syncthreads();
#pragma unroll
    for (int o = 16; o; o >>= 1) mx = fmaxf(mx, __shfl_xor_sync(0xffffffffu, mx, o));
    if ((t & 31) == 0) red[t >> 5] = mx;
    __syncthreads();
    if (t < 8) {
        float mm = red[t];
#pragma unroll
        for (int o = 4; o; o >>= 1) mm = fmaxf(mm, __shfl_xor_sync(0xffu, mm, o));
        if (t == 0) red[0] = mm;
    }
    __syncthreads();
    mx = red[0];
    const float sc = (mx > 0.f) ? mx / 127.f : 1.f;
    const float inv = 127.f * rcpa(fmaxf(mx, 1e-30f));
#pragma unroll
    for (int it = 0; it < 2; it++) {
        int d4 = (it * 256 + t) * 4;
        int a0[4], a1[4];
#pragma unroll
        for (int j = 0; j < 4; j++) {
            float q = y[it*4+j] * inv;
            float r0 = rintf(q);
            a0[j] = (int)r0;
            a1[j] = (int)rintf((q - r0) * 128.f);
        }
        *(uint32_t*)&g_X0[row + d4] = pack4(a0[0],a0[1],a0[2],a0[3]);
        *(uint32_t*)&g_X1[row + d4] = pack4(a1[0],a1[1],a1[2],a1[3]);
    }
    if (t == 0) g_sx[m] = sc;
}

// ---------------------------------------------------------------------------
// Launch
// ---------------------------------------------------------------------------
extern "C" void kernel_launch(void* const* d_in, const int* in_sizes, int n_in,
                              void* d_out, int out_size)
{
    const float* X  = (const float*)d_in[0];
    const float* Wi = (const float*)d_in[1];
    const float* Wf = (const float*)d_in[2];
    const float* Wg = (const float*)d_in[3];
    const float* Wo = (const float*)d_in[4];
    const float* gw = (const float*)d_in[5];
    float* out = (float*)d_out;

    cudaFuncSetAttribute(gemm_mma, cudaFuncAttributeMaxDynamicSharedMemorySize, NSTG * STGB);

    int8_t *x0, *x1, *w0b, *w1b;
    float *sx, *swb;
    cudaGetSymbolAddress((void**)&x0,  g_X0);
    cudaGetSymbolAddress((void**)&x1,  g_X1);
    cudaGetSymbolAddress((void**)&w0b, g_W0);
    cudaGetSymbolAddress((void**)&w1b, g_W1);
    cudaGetSymbolAddress((void**)&sx,  g_sx);
    cudaGetSymbolAddress((void**)&swb, g_sw);
    float *pi, *pf, *pg2;
    cudaGetSymbolAddress((void**)&pi,  g_gate);
    cudaGetSymbolAddress((void**)&pf,  g_v);
    cudaGetSymbolAddress((void**)&pg2, g_gp);

    // quantize X and the 4 weights (2-limb int8, per-row scales)
    quant_rows<<<MM, 256>>>(X, x0, x1, sx);
    quant_rows<<<HH, 256>>>(Wi, w0b + 0*(size_t)HH*HH, w1b + 0*(size_t)HH*HH, swb + 0*HH);
    quant_rows<<<HH, 256>>>(Wf, w0b + 1*(size_t)HH*HH, w1b + 1*(size_t)HH*HH, swb + 1*HH);
    quant_rows<<<HH, 256>>>(Wg, w0b + 2*(size_t)HH*HH, w1b + 2*(size_t)HH*HH, swb + 2*HH);
    quant_rows<<<HH, 256>>>(Wo, w0b + 3*(size_t)HH*HH, w1b + 3*(size_t)HH*HH, swb + 3*HH);

    // i/f/g projections (raw) via int8 tensor cores
    gemm_mma<<<dim3(HH/128, MM/128, 3), 256, NSTG*STGB>>>(x0, x1, sx, 0, pi, pf, pg2);

    // gating (fused) + linear recurrence (scalar R6 grid)
    dim3 scan_grid(HH/256, NCHUNK, BB);
    scan_part1<<<scan_grid, 256>>>();
    scan_part2<<<(BB*HH)/256, 256>>>();
    scan_part3<<<scan_grid, 256>>>();

    // gated RMSNorm -> quantized o (reuses g_X0/g_X1/g_sx)
    norm_kernel<<<MM, 256>>>(gw);

    // output projection -> d_out
    gemm_mma<<<dim3(HH/128, MM/128, 1), 256, NSTG*STGB>>>(x0, x1, sx, 3, out, out, out);
}

// round 11
// speedup vs baseline: 1.9049x; 1.0544x over previous
#include <cuda_runtime.h>
#include <cuda_bf16.h>
#include <cstdint>
#include <math.h>

// Problem constants (fixed: B=4, T=2048, H=2048)
#define BB 4
#define TT 2048
#define HH 2048
#define MM (BB*TT)              // 8192 rows
#define CHUNK 128
#define NCHUNK (TT/CHUNK)       // 16 chunks

// ---------------------------------------------------------------------------
// Scratch (device globals — no runtime allocation allowed)
// ---------------------------------------------------------------------------
__device__ float g_gate[(size_t)MM*HH];   // raw i -> sigmoid(f) after part1
__device__ float g_v[(size_t)MM*HH];      // raw f -> swiglu value after part1
__device__ float g_gp[(size_t)MM*HH];     // raw g projection
__device__ float g_o[(size_t)MM*HH];      // scan output
__device__ float g_Ac[BB*NCHUNK*HH];
__device__ float g_Bc[BB*NCHUNK*HH];
__device__ float g_cr[BB*NCHUNK*HH];
// int8 2-limb quantized operands
__device__ int8_t g_X0[(size_t)MM*HH];    // X limb0 (reused for normed o)
__device__ int8_t g_X1[(size_t)MM*HH];    // X limb1
__device__ int8_t g_W0[4][(size_t)HH*HH];
__device__ int8_t g_W1[4][(size_t)HH*HH];
__device__ float  g_sx[MM];               // per-row scale of X / normed o
__device__ float  g_sw[4][HH];            // per-row scale of each W

// Fast approx reciprocal (single MUFU.RCP, ~2^-22 rel err)
__device__ __forceinline__ float rcpa(float x) {
    float y; asm("rcp.approx.f32 %0, %1;" : "=f"(y) : "f"(x)); return y;
}
// Fast sigmoid: 1 EX2 + 1 RCP
__device__ __forceinline__ float sigf(float x) {
    return rcpa(1.0f + __expf(fminf(-x, 30.0f)));
}

// ---------------------------------------------------------------------------
// PTX helpers (sm_80-era -> valid on compute_100)
// ---------------------------------------------------------------------------
__device__ __forceinline__ uint32_t smem_u32(const void* p) {
    uint32_t a; asm("{ .reg .u64 t; cvta.to.shared.u64 t, %1; cvt.u32.u64 %0, t; }" : "=r"(a) : "l"(p));
    return a;
}
__device__ __forceinline__ void cp16(uint32_t saddr, const void* g) {
    asm volatile("cp.async.cg.shared.global [%0], [%1], 16;" :: "r"(saddr), "l"(g));
}
#define CP_COMMIT() asm volatile("cp.async.commit_group;" ::: "memory")
#define CP_WAIT0()  asm volatile("cp.async.wait_group 0;" ::: "memory")

__device__ __forceinline__ void ldm_x4(uint32_t a, uint32_t* r) {
    asm volatile("ldmatrix.sync.aligned.m8n8.x4.shared.b16 {%0,%1,%2,%3}, [%4];"
        : "=r"(r[0]), "=r"(r[1]), "=r"(r[2]), "=r"(r[3]) : "r"(a));
}
// s8 MMA: m16n8k32, s32 accumulate
__device__ __forceinline__ void mma_s8(int* c, const uint32_t* a, const uint32_t* b) {
    asm volatile("mma.sync.aligned.m16n8k32.row.col.s32.s8.s8.s32 "
        "{%0,%1,%2,%3}, {%4,%5,%6,%7}, {%8,%9}, {%0,%1,%2,%3};"
        : "+r"(c[0]), "+r"(c[1]), "+r"(c[2]), "+r"(c[3])
        : "r"(a[0]), "r"(a[1]), "r"(a[2]), "r"(a[3]), "r"(b[0]), "r"(b[1]));
}

__device__ __forceinline__ uint32_t pack4(int b0, int b1, int b2, int b3) {
    return (uint32_t)(b0 & 255) | ((uint32_t)(b1 & 255) << 8)
         | ((uint32_t)(b2 & 255) << 16) | ((uint32_t)(b3 & 255) << 24);
}

// ---------------------------------------------------------------------------
// Row quantizer: x ~= s*(a0 + a1/128), a0,a1 int8, s = rowmax/127.
// ---------------------------------------------------------------------------
__global__ __launch_bounds__(256) void quant_rows(
    const float* __restrict__ src, int8_t* __restrict__ d0,
    int8_t* __restrict__ d1, float* __restrict__ sarr)
{
    const int row = blockIdx.x;
    const float* x = src + (size_t)row * HH;
    const int t = threadIdx.x;
    float4 v0 = ((const float4*)x)[t*2];
    float4 v1 = ((const float4*)x)[t*2 + 1];
    float xs[8] = {v0.x, v0.y, v0.z, v0.w, v1.x, v1.y, v1.z, v1.w};
    float m = 0.f;
#pragma unroll
    for (int j = 0; j < 8; j++) m = fmaxf(m, fabsf(xs[j]));
    __shared__ float red[8];
#pragma unroll
    for (int o = 16; o; o >>= 1) m = fmaxf(m, __shfl_xor_sync(0xffffffffu, m, o));
    if ((t & 31) == 0) red[t >> 5] = m;
    __syncthreads();
    if (t < 8) {
        float mm = red[t];
#pragma unroll
        for (int o = 4; o; o >>= 1) mm = fmaxf(mm, __shfl_xor_sync(0xffu, mm, o));
        if (t == 0) red[0] = mm;
    }
    __syncthreads();
    m = red[0];
    const float s = (m > 0.f) ? m / 127.f : 1.f;
    const float inv = 127.f * rcpa(fmaxf(m, 1e-30f));
    int a0[8], a1[8];
#pragma unroll
    for (int j = 0; j < 8; j++) {
        float q = xs[j] * inv;
        float r0 = rintf(q);
        a0[j] = (int)r0;
        a1[j] = (int)rintf((q - r0) * 128.f);
    }
    ((uint2*)(d0 + (size_t)row * HH))[t] = make_uint2(pack4(a0[0],a0[1],a0[2],a0[3]), pack4(a0[4],a0[5],a0[6],a0[7]));
    ((uint2*)(d1 + (size_t)row * HH))[t] = make_uint2(pack4(a1[0],a1[1],a1[2],a1[3]), pack4(a1[4],a1[5],a1[6],a1[7]));
    if (t == 0) sarr[row] = s;
}

// ===========================================================================
// 2-limb int8 GEMM on mma.sync m16n8k32: C[m,n] = sum_k A[m,k]*W[n,k]
// CTA 128x64, warp tile 32x32, KC=64, 2-stage cp.async, 2 CTAs/SM.
// Accums 64 regs/thread -> fits 128-reg cap WITHOUT spills (R8 lesson).
// C = sA[m]*sB[n]*(P + Q/128), P = a0w0, Q = a0w1 + a1w0 (a1w1 dropped).
// ===========================================================================
#define KC 64
#define ROWB 80                // conflict-free ldmatrix padding (proven R4-R10)
#define A_MATB (128*ROWB)      // 10240 B per A limb
#define B_MATB (64*ROWB)       // 5120 B per B limb
#define STGB (2*A_MATB + 2*B_MATB)  // 30720 B per stage
#define OFF_A1 A_MATB               // 10240
#define OFF_B0 (2*A_MATB)           // 20480
#define OFF_B1 (2*A_MATB + B_MATB)  // 25600
#define NKC (HH/KC)            // 32 k-iterations

__global__ __launch_bounds__(256, 2) void gemm_mma(
    const int8_t* __restrict__ x0, const int8_t* __restrict__ x1,
    const float* __restrict__ sA, int wbase,
    float* __restrict__ C0, float* __restrict__ C1, float* __restrict__ C2)
{
    extern __shared__ __align__(16) char smem[];
    const uint32_t sb = smem_u32(smem);
    const int tid = threadIdx.x, lane = tid & 31, wid = tid >> 5;
    const int wm = wid >> 1, wn = wid & 1;           // 4x2 warp grid, 32x32 tiles
    const int bm = blockIdx.y * 128, bn = blockIdx.x * 64;
    const int w = wbase + blockIdx.z;
    const int8_t* w0 = g_W0[w];
    const int8_t* w1 = g_W1[w];
    const float* sB = g_sw[w];
    float* C = (blockIdx.z == 0) ? C0 : (blockIdx.z == 1) ? C1 : C2;

    int P[2][4][4] = {}, Q[2][4][4] = {};   // 64 accum regs/thread

    // stage loader: A 1024 vecs + B 512 vecs = 1536, 6 per thread
    auto load_stage = [&](int buf, int k0) {
        const uint32_t sbase = sb + buf * STGB;
#pragma unroll
        for (int i = 0; i < 6; i++) {
            int idx = i * 256 + tid;
            const int8_t* base; uint32_t moff; int row0, r, vv;
            if (i < 4) {                   // A limbs
                int limb = idx >> 9;       // 0..1
                int rem = idx & 511;
                r = rem >> 2; vv = rem & 3;
                base = limb ? x1 : x0;
                moff = limb ? (uint32_t)OFF_A1 : 0u;
                row0 = bm;
            } else {                       // B limbs
                int rem = idx - 1024;
                int limb = rem >> 8;       // 0..1
                rem &= 255;
                r = rem >> 2; vv = rem & 3;
                base = limb ? w1 : w0;
                moff = limb ? (uint32_t)OFF_B1 : (uint32_t)OFF_B0;
                row0 = bn;
            }
            cp16(sbase + moff + (uint32_t)(r * ROWB + vv * 16),
                 base + (size_t)(row0 + r) * HH + k0 + vv * 16);
        }
    };

    const uint32_t aRowOff = (uint32_t)((wm * 32 + (lane & 15)) * ROWB + (lane >> 4) * 16);
    const uint32_t bRowOff = (uint32_t)((wn * 32 + ((lane >> 4) << 3) + (lane & 7)) * ROWB
                                        + ((lane >> 3) & 1) * 16);

    load_stage(0, 0);
    CP_COMMIT();
    CP_WAIT0();
    __syncthreads();

    for (int c = 0; c < NKC; c++) {
        const int buf = c & 1;
        if (c + 1 < NKC) {              // kick next stage before computing
            load_stage(buf ^ 1, (c + 1) * KC);
            CP_COMMIT();
        }
        const uint32_t s0 = sb + buf * STGB;
#pragma unroll
        for (int ks = 0; ks < 2; ks++) {
            const uint32_t kOff = ks * 32;
            uint32_t a0f[2][4], a1f[2][4];
#pragma unroll
            for (int mt = 0; mt < 2; mt++) {
                ldm_x4(s0 + 0      + mt * 16 * ROWB + kOff + aRowOff, a0f[mt]);
                ldm_x4(s0 + OFF_A1 + mt * 16 * ROWB + kOff + aRowOff, a1f[mt]);
            }
#pragma unroll
            for (int p = 0; p < 2; p++) {          // 2 n8-pairs = 32 cols
                uint32_t b0f[4], b1f[4];
                ldm_x4(s0 + OFF_B0 + p * 16 * ROWB + kOff + bRowOff, b0f);
                ldm_x4(s0 + OFF_B1 + p * 16 * ROWB + kOff + bRowOff, b1f);
                mma_s8(P[0][2*p],   a0f[0], &b0f[0]);
                mma_s8(P[1][2*p],   a0f[1], &b0f[0]);
                mma_s8(P[0][2*p+1], a0f[0], &b0f[2]);
                mma_s8(P[1][2*p+1], a0f[1], &b0f[2]);
                mma_s8(Q[0][2*p],   a0f[0], &b1f[0]);
                mma_s8(Q[1][2*p],   a0f[1], &b1f[0]);
                mma_s8(Q[0][2*p+1], a0f[0], &b1f[2]);
                mma_s8(Q[1][2*p+1], a0f[1], &b1f[2]);
                mma_s8(Q[0][2*p],   a1f[0], &b0f[0]);
                mma_s8(Q[1][2*p],   a1f[1], &b0f[0]);
                mma_s8(Q[0][2*p+1], a1f[0], &b0f[2]);
                mma_s8(Q[1][2*p+1], a1f[1], &b0f[2]);
            }
        }
        if (c + 1 < NKC) {
            CP_WAIT0();
            __syncthreads();            // next buf ready AND this buf free
        }
    }

    // Epilogue: C = sA[r]*sB[n]*(P + Q/128)
#pragma unroll
    for (int mt = 0; mt < 2; mt++) {
        const int r0 = bm + wm * 32 + mt * 16 + (lane >> 2);
        const float sa0 = sA[r0], sa1 = sA[r0 + 8];
#pragma unroll
        for (int nt = 0; nt < 4; nt++) {
            const int col = bn + wn * 32 + nt * 8 + (lane & 3) * 2;
            const float sb0 = sB[col], sb1 = sB[col + 1];
            const int* Pp = P[mt][nt];
            const int* Qp = Q[mt][nt];
            float c0 = sa0 * sb0 * ((float)Pp[0] + (float)Qp[0] * (1.f/128.f));
            float c1 = sa0 * sb1 * ((float)Pp[1] + (float)Qp[1] * (1.f/128.f));
            float c2 = sa1 * sb0 * ((float)Pp[2] + (float)Qp[2] * (1.f/128.f));
            float c3 = sa1 * sb1 * ((float)Pp[3] + (float)Qp[3] * (1.f/128.f));
            *(float2*)&C[(size_t)r0 * HH + col]       = make_float2(c0, c1);
            *(float2*)&C[(size_t)(r0 + 8) * HH + col] = make_float2(c2, c3);
        }
    }
}

// ---------------------------------------------------------------------------
// Scan pass 1 + fused gating (scalar, shared-reciprocal) — R10 proven
// ---------------------------------------------------------------------------
__global__ __launch_bounds__(256) void scan_part1()
{
    const int d = blockIdx.x * blockDim.x + threadIdx.x;
    const int c = blockIdx.y, b = blockIdx.z;
    size_t base = ((size_t)(b*TT + c*CHUNK))*HH + d;
    float A = 1.0f, Bv = 0.0f;
#pragma unroll 8
    for (int t = 0; t < CHUNK; t++) {
        const size_t o = base + (size_t)t*HH;
        float iv = g_gate[o];
        float fv = g_v[o];
        float u  = __expf(fminf(-fv, 30.0f));
        float ve = __expf(fminf(-iv, 30.0f));
        float pu = 1.0f + u, pv = 1.0f + ve;
        float r  = rcpa(pu * pv);
        float gate = pv * r;
        float silu = iv * pu * r;
        float vv = silu * (1.0f - gate);
        g_gate[o] = gate;
        g_v[o] = vv;
        Bv = fmaf(gate, Bv, vv);
        A *= gate;
    }
    const size_t co = ((size_t)(b*NCHUNK + c))*HH + d;
    g_Ac[co] = A; g_Bc[co] = Bv;
}
__global__ __launch_bounds__(256) void scan_part2()
{
    const int idx = blockIdx.x * blockDim.x + threadIdx.x;
    const int b = idx / HH, d = idx % HH;
    float h = 0.0f;
    for (int c = 0; c < NCHUNK; c++) {
        const size_t co = ((size_t)(b*NCHUNK + c))*HH + d;
        g_cr[co] = h;
        h = fmaf(g_Ac[co], h, g_Bc[co]);
    }
}
__global__ __launch_bounds__(256) void scan_part3()
{
    const int d = blockIdx.x * blockDim.x + threadIdx.x;
    const int c = blockIdx.y, b = blockIdx.z;
    size_t base = ((size_t)(b*TT + c*CHUNK))*HH + d;
    float h = g_cr[((size_t)(b*NCHUNK + c))*HH + d];
#pragma unroll 8
    for (int t = 0; t < CHUNK; t++) {
        const size_t o = base + (size_t)t*HH;
        h = fmaf(g_gate[o], h, g_v[o]);
        g_o[o] = h;
    }
}

// ---------------------------------------------------------------------------
// Gated RMSNorm; quantizes its output row directly into g_X0/g_X1/g_sx.
// ---------------------------------------------------------------------------
__global__ __launch_bounds__(256) void norm_kernel(const float* __restrict__ w)
{
    const int m = blockIdx.x;
    const size_t row = (size_t)m * HH;
    const int t = threadIdx.x;
    float s = 0.0f;
#pragma unroll
    for (int it = 0; it < 2; it++) {
        int d4 = (it * 256 + t) * 4;
        float4 x = *(const float4*)&g_o[row + d4];
        s = fmaf(x.x, x.x, fmaf(x.y, x.y, fmaf(x.z, x.z, fmaf(x.w, x.w, s))));
    }
    __shared__ float red[8];
#pragma unroll
    for (int o = 16; o; o >>= 1) s += __shfl_xor_sync(0xffffffffu, s, o);
    if ((t & 31) == 0) red[t >> 5] = s;
    __syncthreads();
    if (t < 8) {
        float tt = red[t];
#pragma unroll
        for (int o = 4; o; o >>= 1) tt += __shfl_xor_sync(0xffu, tt, o);
        if (t == 0) red[0] = tt;
    }
    __syncthreads();
    const float rms = rsqrtf(red[0] / (float)HH + 1e-5f);

    float y[8];
    float mx = 0.f;
#pragma unroll
    for (int it = 0; it < 2; it++) {
        int d4 = (it * 256 + t) * 4;
        float4 x  = *(const float4*)&g_o[row + d4];
        float4 gp = *(const float4*)&g_gp[row + d4];
        float4 wv = *(const float4*)&w[d4];
        y[it*4+0] = x.x * rms * wv.x * gp.x * sigf(gp.x);
        y[it*4+1] = x.y * rms * wv.y * gp.y * sigf(gp.y);
        y[it*4+2] = x.z * rms * wv.z * gp.z * sigf(gp.z);
        y[it*4+3] = x.w * rms * wv.w * gp.w * sigf(gp.w);
#pragma unroll
        for (int j = 0; j < 4; j++) mx = fmaxf(mx, fabsf(y[it*4+j]));
    }
    __syncthreads();
#pragma unroll
    for (int o = 16; o; o >>= 1) mx = fmaxf(mx, __shfl_xor_sync(0xffffffffu, mx, o));
    if ((t & 31) == 0) red[t >> 5] = mx;
    __syncthreads();
    if (t < 8) {
        float mm = red[t];
#pragma unroll
        for (int o = 4; o; o >>= 1) mm = fmaxf(mm, __shfl_xor_sync(0xffu, mm, o));
        if (t == 0) red[0] = mm;
    }
    __syncthreads();
    mx = red[0];
    const float sc = (mx > 0.f) ? mx / 127.f : 1.f;
    const float inv = 127.f * rcpa(fmaxf(mx, 1e-30f));
#pragma unroll
    for (int it = 0; it < 2; it++) {
        int d4 = (it * 256 + t) * 4;
        int a0[4], a1[4];
#pragma unroll
        for (int j = 0; j < 4; j++) {
            float q = y[it*4+j] * inv;
            float r0 = rintf(q);
            a0[j] = (int)r0;
            a1[j] = (int)rintf((q - r0) * 128.f);
        }
        *(uint32_t*)&g_X0[row + d4] = pack4(a0[0],a0[1],a0[2],a0[3]);
        *(uint32_t*)&g_X1[row + d4] = pack4(a1[0],a1[1],a1[2],a1[3]);
    }
    if (t == 0) g_sx[m] = sc;
}

// ---------------------------------------------------------------------------
// Launch
// ---------------------------------------------------------------------------
extern "C" void kernel_launch(void* const* d_in, const int* in_sizes, int n_in,
                              void* d_out, int out_size)
{
    const float* X  = (const float*)d_in[0];
    const float* Wi = (const float*)d_in[1];
    const float* Wf = (const float*)d_in[2];
    const float* Wg = (const float*)d_in[3];
    const float* Wo = (const float*)d_in[4];
    const float* gw = (const float*)d_in[5];
    float* out = (float*)d_out;

    cudaFuncSetAttribute(gemm_mma, cudaFuncAttributeMaxDynamicSharedMemorySize, 2 * STGB);

    int8_t *x0, *x1, *w0b, *w1b;
    float *sx, *swb;
    cudaGetSymbolAddress((void**)&x0,  g_X0);
    cudaGetSymbolAddress((void**)&x1,  g_X1);
    cudaGetSymbolAddress((void**)&w0b, g_W0);
    cudaGetSymbolAddress((void**)&w1b, g_W1);
    cudaGetSymbolAddress((void**)&sx,  g_sx);
    cudaGetSymbolAddress((void**)&swb, g_sw);
    float *pi, *pf, *pg2;
    cudaGetSymbolAddress((void**)&pi,  g_gate);
    cudaGetSymbolAddress((void**)&pf,  g_v);
    cudaGetSymbolAddress((void**)&pg2, g_gp);

    // quantize X and the 4 weights (2-limb int8, per-row scales)
    quant_rows<<<MM, 256>>>(X, x0, x1, sx);
    quant_rows<<<HH, 256>>>(Wi, w0b + 0*(size_t)HH*HH, w1b + 0*(size_t)HH*HH, swb + 0*HH);
    quant_rows<<<HH, 256>>>(Wf, w0b + 1*(size_t)HH*HH, w1b + 1*(size_t)HH*HH, swb + 1*HH);
    quant_rows<<<HH, 256>>>(Wg, w0b + 2*(size_t)HH*HH, w1b + 2*(size_t)HH*HH, swb + 2*HH);
    quant_rows<<<HH, 256>>>(Wo, w0b + 3*(size_t)HH*HH, w1b + 3*(size_t)HH*HH, swb + 3*HH);

    // i/f/g projections (raw) via int8 tensor cores — CTA 128x64 tiles
    gemm_mma<<<dim3(HH/64, MM/128, 3), 256, 2*STGB>>>(x0, x1, sx, 0, pi, pf, pg2);

    // gating (fused) + linear recurrence
    dim3 scan_grid(HH/256, NCHUNK, BB);
    scan_part1<<<scan_grid, 256>>>();
    scan_part2<<<(BB*HH)/256, 256>>>();
    scan_part3<<<scan_grid, 256>>>();

    // gated RMSNorm -> quantized o (reuses g_X0/g_X1/g_sx)
    norm_kernel<<<MM, 256>>>(gw);

    // output projection -> d_out
    gemm_mma<<<dim3(HH/64, MM/128, 1), 256, 2*STGB>>>(x0, x1, sx, 3, out, out, out);
}

// round 12
// speedup vs baseline: 1.9831x; 1.0410x over previous
#include <cuda_runtime.h>
#include <cuda_bf16.h>
#include <cstdint>
#include <math.h>

// Problem constants (fixed: B=4, T=2048, H=2048)
#define BB 4
#define TT 2048
#define HH 2048
#define MM (BB*TT)              // 8192 rows

// Scan decomposition (single-pass, decoupled lookback)
#define SC_CHUNK 64
#define SC_NCH (TT/SC_CHUNK)    // 32 chunks
#define SC_N (BB*SC_NCH*HH)     // lookback slots

// ---------------------------------------------------------------------------
// Scratch (device globals — no runtime allocation allowed)
// ---------------------------------------------------------------------------
__device__ float g_gate[(size_t)MM*HH];   // raw i projection (GEMM out)
__device__ float g_v[(size_t)MM*HH];      // raw f projection (GEMM out)
__device__ float g_gp[(size_t)MM*HH];     // raw g projection
__device__ float g_o[(size_t)MM*HH];      // scan output
__device__ float g_aggA[SC_N];            // lookback: chunk aggregate A
__device__ float g_aggB[SC_N];            // lookback: chunk aggregate B
__device__ float g_inc[SC_N];             // lookback: inclusive prefix h
__device__ int   g_flag[SC_N];            // lookback: 0 none / 1 agg / 2 inclusive
// int8 2-limb quantized operands
__device__ int8_t g_X0[(size_t)MM*HH];    // X limb0 (reused for normed o)
__device__ int8_t g_X1[(size_t)MM*HH];    // X limb1
__device__ int8_t g_W0[4][(size_t)HH*HH];
__device__ int8_t g_W1[4][(size_t)HH*HH];
__device__ float  g_sx[MM];               // per-row scale of X / normed o
__device__ float  g_sw[4][HH];            // per-row scale of each W

// Fast approx reciprocal (single MUFU.RCP, ~2^-22 rel err)
__device__ __forceinline__ float rcpa(float x) {
    float y; asm("rcp.approx.f32 %0, %1;" : "=f"(y) : "f"(x)); return y;
}
// Fast sigmoid: 1 EX2 + 1 RCP
__device__ __forceinline__ float sigf(float x) {
    return rcpa(1.0f + __expf(fminf(-x, 30.0f)));
}

// ---------------------------------------------------------------------------
// PTX helpers (sm_80-era -> valid on compute_100)
// ---------------------------------------------------------------------------
__device__ __forceinline__ uint32_t smem_u32(const void* p) {
    uint32_t a; asm("{ .reg .u64 t; cvta.to.shared.u64 t, %1; cvt.u32.u64 %0, t; }" : "=r"(a) : "l"(p));
    return a;
}
__device__ __forceinline__ void cp16(uint32_t saddr, const void* g) {
    asm volatile("cp.async.cg.shared.global [%0], [%1], 16;" :: "r"(saddr), "l"(g));
}
#define CP_COMMIT() asm volatile("cp.async.commit_group;" ::: "memory")
#define CP_WAIT0()  asm volatile("cp.async.wait_group 0;" ::: "memory")

__device__ __forceinline__ void ldm_x4(uint32_t a, uint32_t* r) {
    asm volatile("ldmatrix.sync.aligned.m8n8.x4.shared.b16 {%0,%1,%2,%3}, [%4];"
        : "=r"(r[0]), "=r"(r[1]), "=r"(r[2]), "=r"(r[3]) : "r"(a));
}
// s8 MMA: m16n8k32, s32 accumulate
__device__ __forceinline__ void mma_s8(int* c, const uint32_t* a, const uint32_t* b) {
    asm volatile("mma.sync.aligned.m16n8k32.row.col.s32.s8.s8.s32 "
        "{%0,%1,%2,%3}, {%4,%5,%6,%7}, {%8,%9}, {%0,%1,%2,%3};"
        : "+r"(c[0]), "+r"(c[1]), "+r"(c[2]), "+r"(c[3])
        : "r"(a[0]), "r"(a[1]), "r"(a[2]), "r"(a[3]), "r"(b[0]), "r"(b[1]));
}

__device__ __forceinline__ uint32_t pack4(int b0, int b1, int b2, int b3) {
    return (uint32_t)(b0 & 255) | ((uint32_t)(b1 & 255) << 8)
         | ((uint32_t)(b2 & 255) << 16) | ((uint32_t)(b3 & 255) << 24);
}

// ---------------------------------------------------------------------------
// Lookback flag reset (graph replay leaves flags at 2)
// ---------------------------------------------------------------------------
__global__ __launch_bounds__(256) void reset_flags()
{
    const int i = blockIdx.x * 256 + threadIdx.x;
    ((int4*)g_flag)[i] = make_int4(0, 0, 0, 0);
}

// ---------------------------------------------------------------------------
// Row quantizer: x ~= s*(a0 + a1/128), a0,a1 int8, s = rowmax/127.
// ---------------------------------------------------------------------------
__device__ __forceinline__ void quant_row_body(
    const float* __restrict__ x, int8_t* __restrict__ d0,
    int8_t* __restrict__ d1, float* __restrict__ sarr, int row)
{
    const int t = threadIdx.x;
    float4 v0 = ((const float4*)x)[t*2];
    float4 v1 = ((const float4*)x)[t*2 + 1];
    float xs[8] = {v0.x, v0.y, v0.z, v0.w, v1.x, v1.y, v1.z, v1.w};
    float m = 0.f;
#pragma unroll
    for (int j = 0; j < 8; j++) m = fmaxf(m, fabsf(xs[j]));
    __shared__ float red[8];
#pragma unroll
    for (int o = 16; o; o >>= 1) m = fmaxf(m, __shfl_xor_sync(0xffffffffu, m, o));
    if ((t & 31) == 0) red[t >> 5] = m;
    __syncthreads();
    if (t < 8) {
        float mm = red[t];
#pragma unroll
        for (int o = 4; o; o >>= 1) mm = fmaxf(mm, __shfl_xor_sync(0xffu, mm, o));
        if (t == 0) red[0] = mm;
    }
    __syncthreads();
    m = red[0];
    const float s = (m > 0.f) ? m / 127.f : 1.f;
    const float inv = 127.f * rcpa(fmaxf(m, 1e-30f));
    int a0[8], a1[8];
#pragma unroll
    for (int j = 0; j < 8; j++) {
        float q = xs[j] * inv;
        float r0 = rintf(q);
        a0[j] = (int)r0;
        a1[j] = (int)rintf((q - r0) * 128.f);
    }
    ((uint2*)(d0 + (size_t)row * HH))[t] = make_uint2(pack4(a0[0],a0[1],a0[2],a0[3]), pack4(a0[4],a0[5],a0[6],a0[7]));
    ((uint2*)(d1 + (size_t)row * HH))[t] = make_uint2(pack4(a1[0],a1[1],a1[2],a1[3]), pack4(a1[4],a1[5],a1[6],a1[7]));
    if (t == 0) sarr[row] = s;
}

__global__ __launch_bounds__(256) void quant_x_kernel(const float* __restrict__ src)
{
    const int row = blockIdx.x;
    quant_row_body(src + (size_t)row * HH, g_X0, g_X1, g_sx, row);
}

// All 4 weights in one launch: blockIdx.y selects the weight.
__global__ __launch_bounds__(256) void quant_w_kernel(
    const float* __restrict__ s0, const float* __restrict__ s1,
    const float* __restrict__ s2, const float* __restrict__ s3)
{
    const int row = blockIdx.x;
    const int w = blockIdx.y;
    const float* src = (w == 0) ? s0 : (w == 1) ? s1 : (w == 2) ? s2 : s3;
    quant_row_body(src + (size_t)row * HH, g_W0[w], g_W1[w], g_sw[w], row);
}

// ===========================================================================
// 2-limb int8 GEMM on mma.sync m16n8k32 (EXACT R11 config: 1511 us)
// CTA 128x64, warp tile 32x32, KC=64, 2-stage cp.async, 2 CTAs/SM.
// ===========================================================================
#define KC 64
#define ROWB 80
#define A_MATB (128*ROWB)
#define B_MATB (64*ROWB)
#define STGB (2*A_MATB + 2*B_MATB)
#define OFF_A1 A_MATB
#define OFF_B0 (2*A_MATB)
#define OFF_B1 (2*A_MATB + B_MATB)
#define NKC (HH/KC)

__global__ __launch_bounds__(256, 2) void gemm_mma(
    const int8_t* __restrict__ x0, const int8_t* __restrict__ x1,
    const float* __restrict__ sA, int wbase,
    float* __restrict__ C0, float* __restrict__ C1, float* __restrict__ C2)
{
    extern __shared__ __align__(16) char smem[];
    const uint32_t sb = smem_u32(smem);
    const int tid = threadIdx.x, lane = tid & 31, wid = tid >> 5;
    const int wm = wid >> 1, wn = wid & 1;
    const int bm = blockIdx.y * 128, bn = blockIdx.x * 64;
    const int w = wbase + blockIdx.z;
    const int8_t* w0 = g_W0[w];
    const int8_t* w1 = g_W1[w];
    const float* sB = g_sw[w];
    float* C = (blockIdx.z == 0) ? C0 : (blockIdx.z == 1) ? C1 : C2;

    int P[2][4][4] = {}, Q[2][4][4] = {};

    auto load_stage = [&](int buf, int k0) {
        const uint32_t sbase = sb + buf * STGB;
#pragma unroll
        for (int i = 0; i < 6; i++) {
            int idx = i * 256 + tid;
            const int8_t* base; uint32_t moff; int row0, r, vv;
            if (i < 4) {
                int limb = idx >> 9;
                int rem = idx & 511;
                r = rem >> 2; vv = rem & 3;
                base = limb ? x1 : x0;
                moff = limb ? (uint32_t)OFF_A1 : 0u;
                row0 = bm;
            } else {
                int rem = idx - 1024;
                int limb = rem >> 8;
                rem &= 255;
                r = rem >> 2; vv = rem & 3;
                base = limb ? w1 : w0;
                moff = limb ? (uint32_t)OFF_B1 : (uint32_t)OFF_B0;
                row0 = bn;
            }
            cp16(sbase + moff + (uint32_t)(r * ROWB + vv * 16),
                 base + (size_t)(row0 + r) * HH + k0 + vv * 16);
        }
    };

    const uint32_t aRowOff = (uint32_t)((wm * 32 + (lane & 15)) * ROWB + (lane >> 4) * 16);
    const uint32_t bRowOff = (uint32_t)((wn * 32 + ((lane >> 4) << 3) + (lane & 7)) * ROWB
                                        + ((lane >> 3) & 1) * 16);

    load_stage(0, 0);
    CP_COMMIT();
    CP_WAIT0();
    __syncthreads();

    for (int c = 0; c < NKC; c++) {
        const int buf = c & 1;
        if (c + 1 < NKC) {
            load_stage(buf ^ 1, (c + 1) * KC);
            CP_COMMIT();
        }
        const uint32_t s0 = sb + buf * STGB;
#pragma unroll
        for (int ks = 0; ks < 2; ks++) {
            const uint32_t kOff = ks * 32;
            uint32_t a0f[2][4], a1f[2][4];
#pragma unroll
            for (int mt = 0; mt < 2; mt++) {
                ldm_x4(s0 + 0      + mt * 16 * ROWB + kOff + aRowOff, a0f[mt]);
                ldm_x4(s0 + OFF_A1 + mt * 16 * ROWB + kOff + aRowOff, a1f[mt]);
            }
#pragma unroll
            for (int p = 0; p < 2; p++) {
                uint32_t b0f[4], b1f[4];
                ldm_x4(s0 + OFF_B0 + p * 16 * ROWB + kOff + bRowOff, b0f);
                ldm_x4(s0 + OFF_B1 + p * 16 * ROWB + kOff + bRowOff, b1f);
                mma_s8(P[0][2*p],   a0f[0], &b0f[0]);
                mma_s8(P[1][2*p],   a0f[1], &b0f[0]);
                mma_s8(P[0][2*p+1], a0f[0], &b0f[2]);
                mma_s8(P[1][2*p+1], a0f[1], &b0f[2]);
                mma_s8(Q[0][2*p],   a0f[0], &b1f[0]);
                mma_s8(Q[1][2*p],   a0f[1], &b1f[0]);
                mma_s8(Q[0][2*p+1], a0f[0], &b1f[2]);
                mma_s8(Q[1][2*p+1], a0f[1], &b1f[2]);
                mma_s8(Q[0][2*p],   a1f[0], &b0f[0]);
                mma_s8(Q[1][2*p],   a1f[1], &b0f[0]);
                mma_s8(Q[0][2*p+1], a1f[0], &b0f[2]);
                mma_s8(Q[1][2*p+1], a1f[1], &b0f[2]);
            }
        }
        if (c + 1 < NKC) {
            CP_WAIT0();
            __syncthreads();
        }
    }

#pragma unroll
    for (int mt = 0; mt < 2; mt++) {
        const int r0 = bm + wm * 32 + mt * 16 + (lane >> 2);
        const float sa0 = sA[r0], sa1 = sA[r0 + 8];
#pragma unroll
        for (int nt = 0; nt < 4; nt++) {
            const int col = bn + wn * 32 + nt * 8 + (lane & 3) * 2;
            const float sb0 = sB[col], sb1 = sB[col + 1];
            const int* Pp = P[mt][nt];
            const int* Qp = Q[mt][nt];
            float c0 = sa0 * sb0 * ((float)Pp[0] + (float)Qp[0] * (1.f/128.f));
            float c1 = sa0 * sb1 * ((float)Pp[1] + (float)Qp[1] * (1.f/128.f));
            float c2 = sa1 * sb0 * ((float)Pp[2] + (float)Qp[2] * (1.f/128.f));
            float c3 = sa1 * sb1 * ((float)Pp[3] + (float)Qp[3] * (1.f/128.f));
            *(float2*)&C[(size_t)r0 * HH + col]       = make_float2(c0, c1);
            *(float2*)&C[(size_t)(r0 + 8) * HH + col] = make_float2(c2, c3);
        }
    }
}

// ===========================================================================
// Single-pass fused gating + scan with per-thread decoupled lookback.
// Grid (H/128, B, SC_NCH) — chunk in z (slowest) so predecessors have lower
// linear block id. Each thread owns one d column; gate/v live in smem only.
// ===========================================================================
__global__ __launch_bounds__(128) void scan_fused()
{
    extern __shared__ float sm[];             // [2][SC_CHUNK][128]
    float* smg = sm;
    float* smv = sm + SC_CHUNK * 128;
    const int thr = threadIdx.x;
    const int b = blockIdx.y;
    const int c = blockIdx.z;
    const int d = blockIdx.x * 128 + thr;
    const size_t base = ((size_t)(b * TT + c * SC_CHUNK)) * HH + d;

    // local gating + aggregate
    float A = 1.f, Bv = 0.f;
#pragma unroll 4
    for (int t = 0; t < SC_CHUNK; t++) {
        const size_t o = base + (size_t)t * HH;
        float iv = g_gate[o];                 // raw i
        float fv = g_v[o];                    // raw f
        float u  = __expf(fminf(-fv, 30.f));
        float ve = __expf(fminf(-iv, 30.f));
        float pu = 1.f + u, pv = 1.f + ve;
        float r  = rcpa(pu * pv);
        float gate = pv * r;
        float vv = iv * pu * r * (1.f - gate);
        smg[t * 128 + thr] = gate;
        smv[t * 128 + thr] = vv;
        Bv = fmaf(gate, Bv, vv);
        A *= gate;
    }

    const size_t ci = ((size_t)(c * BB + b)) * HH + d;
    float carry = 0.f;
    if (c == 0) {
        ((volatile float*)g_inc)[ci] = Bv;
        __threadfence();
        ((volatile int*)g_flag)[ci] = 2;
    } else {
        ((volatile float*)g_aggA)[ci] = A;
        ((volatile float*)g_aggB)[ci] = Bv;
        __threadfence();
        ((volatile int*)g_flag)[ci] = 1;
        // lookback over predecessors
        float Aac = 1.f, Bac = 0.f;
        for (int j = c - 1; j >= 0; j--) {
            const size_t cj = ((size_t)(j * BB + b)) * HH + d;
            int f;
            do { f = ((volatile int*)g_flag)[cj]; } while (f == 0);
            __threadfence();
            if (f == 2) {
                float hj = ((volatile float*)g_inc)[cj];
                carry = fmaf(Aac, hj, Bac);
                break;
            } else {
                float Aj = ((volatile float*)g_aggA)[cj];
                float Bj = ((volatile float*)g_aggB)[cj];
                Bac = fmaf(Aac, Bj, Bac);
                Aac = Aac * Aj;
            }
        }
        float inc = fmaf(A, carry, Bv);
        ((volatile float*)g_inc)[ci] = inc;
        __threadfence();
        ((volatile int*)g_flag)[ci] = 2;
    }

    // apply carry, write o
    float h = carry;
#pragma unroll 4
    for (int t = 0; t < SC_CHUNK; t++) {
        h = fmaf(smg[t * 128 + thr], h, smv[t * 128 + thr]);
        g_o[base + (size_t)t * HH] = h;
    }
}

// ---------------------------------------------------------------------------
// Gated RMSNorm; caches o in registers (single read); quantizes output row.
// ---------------------------------------------------------------------------
__global__ __launch_bounds__(256) void norm_kernel(const float* __restrict__ w)
{
    const int m = blockIdx.x;
    const size_t row = (size_t)m * HH;
    const int t = threadIdx.x;
    float xs[8];
    float s = 0.0f;
#pragma unroll
    for (int it = 0; it < 2; it++) {
        int d4 = (it * 256 + t) * 4;
        float4 x = *(const float4*)&g_o[row + d4];
        xs[it*4+0] = x.x; xs[it*4+1] = x.y; xs[it*4+2] = x.z; xs[it*4+3] = x.w;
        s = fmaf(x.x, x.x, fmaf(x.y, x.y, fmaf(x.z, x.z, fmaf(x.w, x.w, s))));
    }
    __shared__ float red[8];
#pragma unroll
    for (int o = 16; o; o >>= 1) s += __shfl_xor_sync(0xffffffffu, s, o);
    if ((t & 31) == 0) red[t >> 5] = s;
    __syncthreads();
    if (t < 8) {
        float tt = red[t];
#pragma unroll
        for (int o = 4; o; o >>= 1) tt += __shfl_xor_sync(0xffu, tt, o);
        if (t == 0) red[0] = tt;
    }
    __syncthreads();
    const float rms = rsqrtf(red[0] / (float)HH + 1e-5f);

    float y[8];
    float mx = 0.f;
#pragma unroll
    for (int it = 0; it < 2; it++) {
        int d4 = (it * 256 + t) * 4;
        float4 gp = *(const float4*)&g_gp[row + d4];
        float4 wv = *(const float4*)&w[d4];
        y[it*4+0] = xs[it*4+0] * rms * wv.x * gp.x * sigf(gp.x);
        y[it*4+1] = xs[it*4+1] * rms * wv.y * gp.y * sigf(gp.y);
        y[it*4+2] = xs[it*4+2] * rms * wv.z * gp.z * sigf(gp.z);
        y[it*4+3] = xs[it*4+3] * rms * wv.w * gp.w * sigf(gp.w);
#pragma unroll
        for (int j = 0; j < 4; j++) mx = fmaxf(mx, fabsf(y[it*4+j]));
    }
    __syncthreads();
#pragma unroll
    for (int o = 16; o; o >>= 1) mx = fmaxf(mx, __shfl_xor_sync(0xffffffffu, mx, o));
    if ((t & 31) == 0) red[t >> 5] = mx;
    __syncthreads();
    if (t < 8) {
        float mm = red[t];
#pragma unroll
        for (int o = 4; o; o >>= 1) mm = fmaxf(mm, __shfl_xor_sync(0xffu, mm, o));
        if (t == 0) red[0] = mm;
    }
    __syncthreads();
    mx = red[0];
    const float sc = (mx > 0.f) ? mx / 127.f : 1.f;
    const float inv = 127.f * rcpa(fmaxf(mx, 1e-30f));
#pragma unroll
    for (int it = 0; it < 2; it++) {
        int d4 = (it * 256 + t) * 4;
        int a0[4], a1[4];
#pragma unroll
        for (int j = 0; j < 4; j++) {
            float q = y[it*4+j] * inv;
            float r0 = rintf(q);
            a0[j] = (int)r0;
            a1[j] = (int)rintf((q - r0) * 128.f);
        }
        *(uint32_t*)&g_X0[row + d4] = pack4(a0[0],a0[1],a0[2],a0[3]);
        *(uint32_t*)&g_X1[row + d4] = pack4(a1[0],a1[1],a1[2],a1[3]);
    }
    if (t == 0) g_sx[m] = sc;
}

// ---------------------------------------------------------------------------
// Launch
// ---------------------------------------------------------------------------
extern "C" void kernel_launch(void* const* d_in, const int* in_sizes, int n_in,
                              void* d_out, int out_size)
{
    const float* X  = (const float*)d_in[0];
    const float* Wi = (const float*)d_in[1];
    const float* Wf = (const float*)d_in[2];
    const float* Wg = (const float*)d_in[3];
    const float* Wo = (const float*)d_in[4];
    const float* gw = (const float*)d_in[5];
    float* out = (float*)d_out;

    cudaFuncSetAttribute(gemm_mma,  cudaFuncAttributeMaxDynamicSharedMemorySize, 2 * STGB);
    cudaFuncSetAttribute(scan_fused, cudaFuncAttributeMaxDynamicSharedMemorySize,
                         2 * SC_CHUNK * 128 * (int)sizeof(float));

    int8_t *x0, *x1;
    float *sx;
    cudaGetSymbolAddress((void**)&x0,  g_X0);
    cudaGetSymbolAddress((void**)&x1,  g_X1);
    cudaGetSymbolAddress((void**)&sx,  g_sx);
    float *pi, *pf, *pg2;
    cudaGetSymbolAddress((void**)&pi,  g_gate);
    cudaGetSymbolAddress((void**)&pf,  g_v);
    cudaGetSymbolAddress((void**)&pg2, g_gp);

    // reset lookback flags (graph replay leaves them set)
    reset_flags<<<SC_N / 4 / 256, 256>>>();

    // quantize X and the 4 weights (2-limb int8, per-row scales)
    quant_x_kernel<<<MM, 256>>>(X);
    quant_w_kernel<<<dim3(HH, 4), 256>>>(Wi, Wf, Wg, Wo);

    // i/f/g projections (raw) via int8 tensor cores — CTA 128x64 tiles
    gemm_mma<<<dim3(HH/64, MM/128, 3), 256, 2*STGB>>>(x0, x1, sx, 0, pi, pf, pg2);

    // fused gating + linear recurrence (single pass, decoupled lookback)
    scan_fused<<<dim3(HH/128, BB, SC_NCH), 128,
                 2 * SC_CHUNK * 128 * sizeof(float)>>>();

    // gated RMSNorm -> quantized o (reuses g_X0/g_X1/g_sx)
    norm_kernel<<<MM, 256>>>(gw);

    // output projection -> d_out
    gemm_mma<<<dim3(HH/64, MM/128, 1), 256, 2*STGB>>>(x0, x1, sx, 3, out, out, out);
}